// round 3
// baseline (speedup 1.0000x reference)
#include <cuda_runtime.h>
#include <math.h>

#define LQ 1024
#define BB 16
#define FF 512
#define HH 8
#define KK 64
#define TEMPS 30.0f

typedef unsigned long long ull;

// Scratch: normalized projections, layout [B][H][L][K] so each (b,h) matrix is contiguous.
__device__ float g_wq[(size_t)BB * HH * LQ * KK];
__device__ float g_wk[(size_t)BB * HH * LQ * KK];

// packed fp32x2 FMA: d = a*b + d (elementwise on the two fp32 halves)
__device__ __forceinline__ void ffma2(ull& d, ull a, ull b) {
    asm("fma.rn.f32x2 %0, %1, %2, %0;" : "+l"(d) : "l"(a), "l"(b));
}
// duplicate a float into both halves of a b64
__device__ __forceinline__ ull dup2(float x) {
    ull r;
    asm("mov.b64 %0, {%1, %1};" : "=l"(r) : "f"(x));
    return r;
}

// ---------------------------------------------------------------------------
// Kernel 1: C[M,512] = X[M,512] @ W[512,512]^T + bias, then L2-normalize each
// 64-wide head group. Tile 64x64, BK=16, 256 threads, 4x4 per thread (FFMA2).
// ---------------------------------------------------------------------------
__global__ __launch_bounds__(256) void proj_kernel(const float* __restrict__ X,
                                                   const float* __restrict__ W,
                                                   const float* __restrict__ bias,
                                                   float* __restrict__ outp) {
    __shared__ __align__(16) float As[16][68];
    __shared__ __align__(16) float Bs[16][68];
    __shared__ __align__(16) float Cs[64][68];
    __shared__ float scl[64];

    const int tid = threadIdx.x;
    const int tx = tid & 15, ty = tid >> 4;
    const int m0 = blockIdx.x * 64;
    const int h = blockIdx.y;
    const int n0 = h * 64;

    ull acc[4][2];
#pragma unroll
    for (int i = 0; i < 4; i++) { acc[i][0] = 0ull; acc[i][1] = 0ull; }

    const int lrow = tid >> 2;        // 0..63
    const int lk4 = (tid & 3) * 4;    // 0,4,8,12

    const float* Xp = X + (size_t)(m0 + lrow) * FF + lk4;
    const float* Wp = W + (size_t)(n0 + lrow) * FF + lk4;

    for (int k0 = 0; k0 < FF; k0 += 16) {
        float4 a = *(const float4*)(Xp + k0);
        float4 w = *(const float4*)(Wp + k0);
        As[lk4 + 0][lrow] = a.x; As[lk4 + 1][lrow] = a.y;
        As[lk4 + 2][lrow] = a.z; As[lk4 + 3][lrow] = a.w;
        Bs[lk4 + 0][lrow] = w.x; Bs[lk4 + 1][lrow] = w.y;
        Bs[lk4 + 2][lrow] = w.z; Bs[lk4 + 3][lrow] = w.w;
        __syncthreads();
#pragma unroll
        for (int k = 0; k < 16; k++) {
            float4 av = *(const float4*)&As[k][ty * 4];
            ulonglong2 bw = *(const ulonglong2*)&Bs[k][tx * 4];
            ull a0 = dup2(av.x), a1 = dup2(av.y), a2 = dup2(av.z), a3 = dup2(av.w);
            ffma2(acc[0][0], a0, bw.x); ffma2(acc[0][1], a0, bw.y);
            ffma2(acc[1][0], a1, bw.x); ffma2(acc[1][1], a1, bw.y);
            ffma2(acc[2][0], a2, bw.x); ffma2(acc[2][1], a2, bw.y);
            ffma2(acc[3][0], a3, bw.x); ffma2(acc[3][1], a3, bw.y);
        }
        __syncthreads();
    }

    // bias + stage tile to smem
    float bj[4];
#pragma unroll
    for (int j = 0; j < 4; j++) bj[j] = bias[n0 + tx * 4 + j];
#pragma unroll
    for (int i = 0; i < 4; i++) {
        float2 f0 = *(float2*)&acc[i][0];
        float2 f1 = *(float2*)&acc[i][1];
        Cs[ty * 4 + i][tx * 4 + 0] = f0.x + bj[0];
        Cs[ty * 4 + i][tx * 4 + 1] = f0.y + bj[1];
        Cs[ty * 4 + i][tx * 4 + 2] = f1.x + bj[2];
        Cs[ty * 4 + i][tx * 4 + 3] = f1.y + bj[3];
    }
    __syncthreads();

    // per-row (= per (q,b,h) vector) L2 norm, matching torch F.normalize eps
    if (tid < 64) {
        float ss = 0.f;
#pragma unroll 8
        for (int c = 0; c < 64; c++) {
            float v = Cs[tid][c];
            ss = fmaf(v, v, ss);
        }
        float nrm = sqrtf(ss);
        scl[tid] = 1.0f / fmaxf(nrm, 1e-12f);
    }
    __syncthreads();

#pragma unroll
    for (int i = 0; i < 4; i++) {
        int m = m0 + ty * 4 + i;
        int q = m >> 4;        // B = 16
        int b = m & 15;
        float s = scl[ty * 4 + i];
        float4 o;
        o.x = Cs[ty * 4 + i][tx * 4 + 0] * s;
        o.y = Cs[ty * 4 + i][tx * 4 + 1] * s;
        o.z = Cs[ty * 4 + i][tx * 4 + 2] * s;
        o.w = Cs[ty * 4 + i][tx * 4 + 3] * s;
        *(float4*)(outp + (((size_t)(b * HH + h) * LQ + q) * KK) + tx * 4) = o;
    }
}

// ---------------------------------------------------------------------------
// Kernel 2: attention for one (b, h, 32-row q-tile).
//   Phase A: S[32,1024] = Q[32,64] @ K^T * TEMP  (scores in smem, FFMA2)
//   Phase B: exact softmax per row
//   Phase C: O[32,512] = P @ V_b (FFMA2, 8 rows x 8 cols per thread)
// ---------------------------------------------------------------------------
__global__ __launch_bounds__(256, 1) void attn_kernel(const float* __restrict__ value,
                                                      float* __restrict__ out) {
    extern __shared__ __align__(16) float sm[];
    float* sc = sm;                       // 32*1024
    float* Qs = sm + 32 * 1024;           // 32*64
    float* Kst = Qs + 32 * 64;            // [k][s] 64*68
    float* inv = Kst + 64 * 68;           // 32

    const int tid = threadIdx.x;
    const int q0 = blockIdx.x * 32;
    const int h = blockIdx.y;
    const int b = blockIdx.z;

    const float* qbase = g_wq + ((size_t)(b * HH + h) * LQ + q0) * KK;
    const float* kbase = g_wk + (size_t)(b * HH + h) * LQ * KK;

    // load Q tile (2048 floats)
    for (int i = tid; i < 32 * 64 / 4; i += 256)
        ((float4*)Qs)[i] = ((const float4*)qbase)[i];

    const int tx = tid & 15, ty = tid >> 4;

    // ---------------- Phase A: scores ----------------
    for (int st = 0; st < 16; st++) {
        const float* kp = kbase + (size_t)st * 64 * KK;
        const int sr = tid >> 2;
        const int kb = (tid & 3) * 16;
#pragma unroll
        for (int u = 0; u < 4; u++) {
            float4 v = *(const float4*)(kp + sr * 64 + kb + u * 4);
            Kst[(kb + u * 4 + 0) * 68 + sr] = v.x;
            Kst[(kb + u * 4 + 1) * 68 + sr] = v.y;
            Kst[(kb + u * 4 + 2) * 68 + sr] = v.z;
            Kst[(kb + u * 4 + 3) * 68 + sr] = v.w;
        }
        __syncthreads();

        ull a0[2] = {0ull, 0ull}, a1[2] = {0ull, 0ull};
        const float* qr0 = Qs + (ty * 2) * 64;
        const float* qr1 = qr0 + 64;
#pragma unroll 16
        for (int k = 0; k < 64; k++) {
            ull qa = dup2(qr0[k]);
            ull qb = dup2(qr1[k]);
            ulonglong2 kv = *(const ulonglong2*)&Kst[k * 68 + tx * 4];
            ffma2(a0[0], qa, kv.x); ffma2(a0[1], qa, kv.y);
            ffma2(a1[0], qb, kv.x); ffma2(a1[1], qb, kv.y);
        }
        float2 u00 = *(float2*)&a0[0], u01 = *(float2*)&a0[1];
        float2 u10 = *(float2*)&a1[0], u11 = *(float2*)&a1[1];
        float4 s0 = make_float4(u00.x * TEMPS, u00.y * TEMPS, u01.x * TEMPS, u01.y * TEMPS);
        float4 s1 = make_float4(u10.x * TEMPS, u10.y * TEMPS, u11.x * TEMPS, u11.y * TEMPS);
        *(float4*)&sc[(ty * 2) * 1024 + st * 64 + tx * 4] = s0;
        *(float4*)&sc[(ty * 2 + 1) * 1024 + st * 64 + tx * 4] = s1;
        __syncthreads();
    }

    // ---------------- Phase B: softmax (one warp : 4 rows) ----------------
    const int w = tid >> 5, lane = tid & 31;
#pragma unroll
    for (int i = 0; i < 4; i++) {
        const int r = w * 4 + i;
        float* row = sc + r * 1024;
        float m = -1e30f;
        for (int s = lane; s < 1024; s += 32) m = fmaxf(m, row[s]);
#pragma unroll
        for (int o = 16; o; o >>= 1) m = fmaxf(m, __shfl_xor_sync(0xFFFFFFFFu, m, o));
        float sum = 0.f;
        for (int s = lane; s < 1024; s += 32) {
            float e = __expf(row[s] - m);
            row[s] = e;
            sum += e;
        }
#pragma unroll
        for (int o = 16; o; o >>= 1) sum += __shfl_xor_sync(0xFFFFFFFFu, sum, o);
        if (lane == 0) inv[r] = 1.0f / sum;
    }
    __syncthreads();

    // ---------------- Phase C: O = P @ V ----------------
    // warp w: rowg = w>>1 (8 rows), colg = w&1 (256 cols); thread: 8 rows x 8 cols.
    const int rowg = w >> 1;
    const int colg = w & 1;
    const int r0 = rowg * 8;
    const float* vbase = value + (size_t)b * FF + colg * 256 + lane * 4;

    ull acc[8][4];
#pragma unroll
    for (int i = 0; i < 8; i++)
#pragma unroll
        for (int j = 0; j < 4; j++) acc[i][j] = 0ull;

    for (int s0 = 0; s0 < LQ; s0 += 4) {
        float4 p4[8];
#pragma unroll
        for (int i = 0; i < 8; i++)
            p4[i] = *(const float4*)&sc[(r0 + i) * 1024 + s0];
#pragma unroll
        for (int u = 0; u < 4; u++) {
            const float* vp = vbase + (size_t)(s0 + u) * (BB * FF);
            ulonglong2 va = *(const ulonglong2*)vp;
            ulonglong2 vb = *(const ulonglong2*)(vp + 128);
#pragma unroll
            for (int i = 0; i < 8; i++) {
                float p = (u == 0) ? p4[i].x : (u == 1) ? p4[i].y : (u == 2) ? p4[i].z : p4[i].w;
                ull pp = dup2(p);
                ffma2(acc[i][0], pp, va.x);
                ffma2(acc[i][1], pp, va.y);
                ffma2(acc[i][2], pp, vb.x);
                ffma2(acc[i][3], pp, vb.y);
            }
        }
    }

#pragma unroll
    for (int i = 0; i < 8; i++) {
        const int q = q0 + r0 + i;
        const float iv = inv[r0 + i];
        float* op = out + ((size_t)q * BB + b) * (HH * FF) + h * FF + colg * 256 + lane * 4;
        float2 f0 = *(float2*)&acc[i][0];
        float2 f1 = *(float2*)&acc[i][1];
        float2 f2 = *(float2*)&acc[i][2];
        float2 f3 = *(float2*)&acc[i][3];
        float4 o0 = make_float4(f0.x * iv, f0.y * iv, f1.x * iv, f1.y * iv);
        float4 o1 = make_float4(f2.x * iv, f2.y * iv, f3.x * iv, f3.y * iv);
        *(float4*)(op) = o0;
        *(float4*)(op + 128) = o1;
    }
}

// ---------------------------------------------------------------------------
extern "C" void kernel_launch(void* const* d_in, const int* in_sizes, int n_in,
                              void* d_out, int out_size) {
    const float* query = (const float*)d_in[0];  // [1024,16,512]
    const float* key   = (const float*)d_in[1];  // [1024,16,512]
    const float* value = (const float*)d_in[2];  // [1024,16,512]
    const float* Wk    = (const float*)d_in[3];  // [8,64,512] == [512,512] row-major
    const float* bk    = (const float*)d_in[4];  // [8,64] == [512]
    float* out = (float*)d_out;                  // [1024,16,4096]

    float *wq, *wk;
    cudaGetSymbolAddress((void**)&wq, g_wq);
    cudaGetSymbolAddress((void**)&wk, g_wk);

    dim3 pg((LQ * BB) / 64, HH);  // (256, 8)
    proj_kernel<<<pg, 256>>>(query, Wk, bk, wq);
    proj_kernel<<<pg, 256>>>(key, Wk, bk, wk);

    const size_t smem = (size_t)(32 * 1024 + 32 * 64 + 64 * 68 + 32) * sizeof(float);
    cudaFuncSetAttribute(attn_kernel, cudaFuncAttributeMaxDynamicSharedMemorySize, (int)smem);
    dim3 ag(LQ / 32, HH, BB);     // (32, 8, 16)
    attn_kernel<<<ag, 256, smem>>>(value, out);
}

// round 9
// speedup vs baseline: 1.7083x; 1.7083x over previous
#include <cuda_runtime.h>
#include <cuda_bf16.h>
#include <cuda_fp16.h>
#include <math.h>
#include <stdint.h>

#define LQ 1024
#define BB 16
#define FF 512
#define HH 8
#define KK 64
#define TEMPS 30.0f

// ------------------------- static scratch -------------------------
// split-bf16 parts of normalized projections, [b][h][l][64] k-contig
__device__ __nv_bfloat16 g_wq1[(size_t)BB * HH * LQ * KK];
__device__ __nv_bfloat16 g_wq2[(size_t)BB * HH * LQ * KK];
__device__ __nv_bfloat16 g_wq3[(size_t)BB * HH * LQ * KK];
__device__ __nv_bfloat16 g_wk1[(size_t)BB * HH * LQ * KK];
__device__ __nv_bfloat16 g_wk2[(size_t)BB * HH * LQ * KK];
__device__ __nv_bfloat16 g_wk3[(size_t)BB * HH * LQ * KK];
// V transposed+split: [b][f][s], uint32 = (lo16<<16)|hi16 fp16
__device__ uint32_t g_vt[(size_t)BB * FF * LQ];
// exp(scores) fp32
__device__ float g_S[(size_t)BB * HH * LQ * LQ];
// row partial sums (32 x 32-col partials per row)
__device__ float g_ps[(size_t)BB * HH * LQ * 32];

// ------------------------- helpers -------------------------
__device__ __forceinline__ void split3(float x, __nv_bfloat16& a, __nv_bfloat16& b, __nv_bfloat16& c) {
    a = __float2bfloat16(x);
    float r = x - __bfloat162float(a);
    b = __float2bfloat16(r);
    c = __float2bfloat16(r - __bfloat162float(b));
}

__device__ __forceinline__ void mma_bf16(float c[4], uint32_t a0, uint32_t a1, uint32_t a2,
                                         uint32_t a3, uint32_t b0, uint32_t b1) {
    asm("mma.sync.aligned.m16n8k16.row.col.f32.bf16.bf16.f32 "
        "{%0,%1,%2,%3}, {%4,%5,%6,%7}, {%8,%9}, {%0,%1,%2,%3};"
        : "+f"(c[0]), "+f"(c[1]), "+f"(c[2]), "+f"(c[3])
        : "r"(a0), "r"(a1), "r"(a2), "r"(a3), "r"(b0), "r"(b1));
}
__device__ __forceinline__ void mma_f16(float c[4], uint32_t a0, uint32_t a1, uint32_t a2,
                                        uint32_t a3, uint32_t b0, uint32_t b1) {
    asm("mma.sync.aligned.m16n8k16.row.col.f32.f16.f16.f32 "
        "{%0,%1,%2,%3}, {%4,%5,%6,%7}, {%8,%9}, {%0,%1,%2,%3};"
        : "+f"(c[0]), "+f"(c[1]), "+f"(c[2]), "+f"(c[3])
        : "r"(a0), "r"(a1), "r"(a2), "r"(a3), "r"(b0), "r"(b1));
}

// ---------------------------------------------------------------------------
// Kernel 1: projection + bias + L2-normalize (SIMT fp32); writes 3-way
// split-bf16 parts. scale folds TEMP for Q.
// ---------------------------------------------------------------------------
__global__ __launch_bounds__(256) void proj_kernel(const float* __restrict__ X,
                                                   const float* __restrict__ W,
                                                   const float* __restrict__ bias,
                                                   __nv_bfloat16* __restrict__ o1,
                                                   __nv_bfloat16* __restrict__ o2,
                                                   __nv_bfloat16* __restrict__ o3,
                                                   float scale) {
    __shared__ __align__(16) float As[16][68];
    __shared__ __align__(16) float Bs[16][68];
    __shared__ __align__(16) float Cs[64][68];
    __shared__ float scl[64];

    const int tid = threadIdx.x;
    const int tx = tid & 15, ty = tid >> 4;
    const int m0 = blockIdx.x * 64;
    const int h = blockIdx.y;
    const int n0 = h * 64;

    float acc[4][4] = {};
    const int lrow = tid >> 2;
    const int lk4 = (tid & 3) * 4;

    const float* Xp = X + (size_t)(m0 + lrow) * FF + lk4;
    const float* Wp = W + (size_t)(n0 + lrow) * FF + lk4;

    for (int k0 = 0; k0 < FF; k0 += 16) {
        float4 a = *(const float4*)(Xp + k0);
        float4 w = *(const float4*)(Wp + k0);
        As[lk4 + 0][lrow] = a.x; As[lk4 + 1][lrow] = a.y;
        As[lk4 + 2][lrow] = a.z; As[lk4 + 3][lrow] = a.w;
        Bs[lk4 + 0][lrow] = w.x; Bs[lk4 + 1][lrow] = w.y;
        Bs[lk4 + 2][lrow] = w.z; Bs[lk4 + 3][lrow] = w.w;
        __syncthreads();
#pragma unroll
        for (int k = 0; k < 16; k++) {
            float4 av = *(const float4*)&As[k][ty * 4];
            float4 bw = *(const float4*)&Bs[k][tx * 4];
            float aa[4] = {av.x, av.y, av.z, av.w};
            float ww[4] = {bw.x, bw.y, bw.z, bw.w};
#pragma unroll
            for (int i = 0; i < 4; i++)
#pragma unroll
                for (int j = 0; j < 4; j++)
                    acc[i][j] = fmaf(aa[i], ww[j], acc[i][j]);
        }
        __syncthreads();
    }

    float bj[4];
#pragma unroll
    for (int j = 0; j < 4; j++) bj[j] = bias[n0 + tx * 4 + j];
#pragma unroll
    for (int i = 0; i < 4; i++)
#pragma unroll
        for (int j = 0; j < 4; j++)
            Cs[ty * 4 + i][tx * 4 + j] = acc[i][j] + bj[j];
    __syncthreads();

    if (tid < 64) {
        float ss = 0.f;
#pragma unroll 8
        for (int c = 0; c < 64; c++) {
            float v = Cs[tid][c];
            ss = fmaf(v, v, ss);
        }
        scl[tid] = scale / fmaxf(sqrtf(ss), 1e-12f);
    }
    __syncthreads();

#pragma unroll
    for (int i = 0; i < 4; i++) {
        int m = m0 + ty * 4 + i;
        int q = m >> 4;
        int b = m & 15;
        float s = scl[ty * 4 + i];
        float v[4];
#pragma unroll
        for (int j = 0; j < 4; j++) v[j] = Cs[ty * 4 + i][tx * 4 + j] * s;
        __nv_bfloat16 p1[4], p2[4], p3[4];
#pragma unroll
        for (int j = 0; j < 4; j++) split3(v[j], p1[j], p2[j], p3[j]);
        size_t off = (((size_t)(b * HH + h) * LQ + q) * KK) + tx * 4;
        __nv_bfloat162 t;
        t = __halves2bfloat162(p1[0], p1[1]); *(uint32_t*)(o1 + off)     = *(uint32_t*)&t;
        t = __halves2bfloat162(p1[2], p1[3]); *(uint32_t*)(o1 + off + 2) = *(uint32_t*)&t;
        t = __halves2bfloat162(p2[0], p2[1]); *(uint32_t*)(o2 + off)     = *(uint32_t*)&t;
        t = __halves2bfloat162(p2[2], p2[3]); *(uint32_t*)(o2 + off + 2) = *(uint32_t*)&t;
        t = __halves2bfloat162(p3[0], p3[1]); *(uint32_t*)(o3 + off)     = *(uint32_t*)&t;
        t = __halves2bfloat162(p3[2], p3[3]); *(uint32_t*)(o3 + off + 2) = *(uint32_t*)&t;
    }
}

// ---------------------------------------------------------------------------
// Kernel 2: V transpose + fp16 hi/lo split, packed: g_vt[b][f][s]
// ---------------------------------------------------------------------------
__global__ void vsplit_kernel(const float* __restrict__ value) {
    __shared__ float t[32][33];
    const int x = threadIdx.x, ty = threadIdx.y;
    const int f0 = blockIdx.x * 32, s0 = blockIdx.y * 32, b = blockIdx.z;
#pragma unroll
    for (int r = 0; r < 4; r++) {
        int s = ty + r * 8;
        t[s][x] = value[(size_t)(s0 + s) * (BB * FF) + b * FF + f0 + x];
    }
    __syncthreads();
#pragma unroll
    for (int r = 0; r < 4; r++) {
        int f = ty + r * 8;
        float v = t[x][f];
        __half h = __float2half_rn(v);
        __half l = __float2half_rn(v - __half2float(h));
        g_vt[((size_t)(b * FF + f0 + f)) * LQ + s0 + x] =
            ((uint32_t)__half_as_ushort(l) << 16) | (uint32_t)__half_as_ushort(h);
    }
}

// ---------------------------------------------------------------------------
// Kernel 3: scores. CTA (qt, nt, h, b) = 128q x 64n; warp = 32q x 32n.
// S = wq@wk^T via split-bf16 mma (6 passes). Epilogue: exp + partial sums.
// ---------------------------------------------------------------------------
__global__ __launch_bounds__(256) void scores_kernel() {
    const int tid = threadIdx.x;
    const int w = tid >> 5, lane = tid & 31;
    const int g = lane >> 2, tig = lane & 3;
    const int qw = w >> 1, fw = w & 1;
    const int bx = blockIdx.x;
    const int qt = bx >> 4, nt = bx & 15;
    const int h = blockIdx.y, b = blockIdx.z;
    const size_t bh = (size_t)(b * HH + h);

    const size_t abase = (bh * LQ + qt * 128 + qw * 32) * KK;
    const size_t bbase = (bh * LQ + nt * 64 + fw * 32) * KK;
    const __nv_bfloat16* Ap[3] = {g_wq1 + abase, g_wq2 + abase, g_wq3 + abase};
    const __nv_bfloat16* Bp[3] = {g_wk1 + bbase, g_wk2 + bbase, g_wk3 + bbase};

    float acc[2][4][4] = {};

#pragma unroll
    for (int kc = 0; kc < 4; kc++) {
        uint32_t au[3][2][4];
#pragma unroll
        for (int p = 0; p < 3; p++)
#pragma unroll
            for (int mi = 0; mi < 2; mi++) {
                const __nv_bfloat16* ptr = Ap[p] + (mi * 16 + g) * KK + kc * 16 + tig * 2;
                au[p][mi][0] = *(const uint32_t*)(ptr);
                au[p][mi][1] = *(const uint32_t*)(ptr + 8 * KK);
                au[p][mi][2] = *(const uint32_t*)(ptr + 8);
                au[p][mi][3] = *(const uint32_t*)(ptr + 8 * KK + 8);
            }
#pragma unroll
        for (int ni = 0; ni < 4; ni++) {
            uint32_t bu[3][2];
#pragma unroll
            for (int p = 0; p < 3; p++) {
                const __nv_bfloat16* ptr = Bp[p] + (ni * 8 + g) * KK + kc * 16 + tig * 2;
                bu[p][0] = *(const uint32_t*)(ptr);
                bu[p][1] = *(const uint32_t*)(ptr + 8);
            }
            // passes: (1,1),(1,2),(2,1),(2,2),(1,3),(3,1)
            const int pa[6] = {0, 0, 1, 1, 0, 2};
            const int pb[6] = {0, 1, 0, 1, 2, 0};
#pragma unroll
            for (int p = 0; p < 6; p++)
#pragma unroll
                for (int mi = 0; mi < 2; mi++)
                    mma_bf16(acc[mi][ni], au[pa[p]][mi][0], au[pa[p]][mi][1],
                             au[pa[p]][mi][2], au[pa[p]][mi][3], bu[pb[p]][0], bu[pb[p]][1]);
        }
    }

    // epilogue: exp + store + per-32col partial row sums
#pragma unroll
    for (int mi = 0; mi < 2; mi++) {
        const int row0 = qt * 128 + qw * 32 + mi * 16 + g;
        float sum0 = 0.f, sum1 = 0.f;
#pragma unroll
        for (int ni = 0; ni < 4; ni++) {
            float e0 = __expf(acc[mi][ni][0]);
            float e1 = __expf(acc[mi][ni][1]);
            float e2 = __expf(acc[mi][ni][2]);
            float e3 = __expf(acc[mi][ni][3]);
            sum0 += e0 + e1;
            sum1 += e2 + e3;
            const int col = nt * 64 + fw * 32 + ni * 8 + tig * 2;
            *(float2*)(g_S + (bh * LQ + row0) * 1024 + col) = make_float2(e0, e1);
            *(float2*)(g_S + (bh * LQ + row0 + 8) * 1024 + col) = make_float2(e2, e3);
        }
        sum0 += __shfl_xor_sync(0xFFFFFFFFu, sum0, 1);
        sum0 += __shfl_xor_sync(0xFFFFFFFFu, sum0, 2);
        sum1 += __shfl_xor_sync(0xFFFFFFFFu, sum1, 1);
        sum1 += __shfl_xor_sync(0xFFFFFFFFu, sum1, 2);
        if (tig == 0) {
            const int pidx = nt * 2 + fw;
            g_ps[(bh * LQ + row0) * 32 + pidx] = sum0;
            g_ps[(bh * LQ + row0 + 8) * 32 + pidx] = sum1;
        }
    }
}

// ---------------------------------------------------------------------------
// Kernel 4: P@V. CTA (qt, ft, h, b) = 128q x 256f; 512 thr; warp = 32q x 64f.
// A = exp(S)*inv -> fp16 inline; B = packed hi/lo fp16 V (PRMT unpack).
// ---------------------------------------------------------------------------
__global__ __launch_bounds__(512) void pv_kernel(float* __restrict__ out) {
    __shared__ float sm_iv[128];
    const int tid = threadIdx.x;
    const int w = tid >> 5, lane = tid & 31;
    const int g = lane >> 2, tig = lane & 3;
    const int qw = w & 3, fw = w >> 2;
    const int qt = blockIdx.x >> 1, ft = blockIdx.x & 1;
    const int h = blockIdx.y, b = blockIdx.z;
    const size_t bh = (size_t)(b * HH + h);

    // row inverse sums
    if (tid < 128) {
        const float4* pp = (const float4*)(g_ps + (bh * LQ + qt * 128 + tid) * 32);
        float s = 0.f;
#pragma unroll
        for (int i = 0; i < 8; i++) {
            float4 v = pp[i];
            s += v.x + v.y + v.z + v.w;
        }
        sm_iv[tid] = 1.0f / s;
    }
    __syncthreads();

    float iv[2][2];
#pragma unroll
    for (int mi = 0; mi < 2; mi++) {
        iv[mi][0] = sm_iv[qw * 32 + mi * 16 + g];
        iv[mi][1] = sm_iv[qw * 32 + mi * 16 + g + 8];
    }

    const float* pA = g_S + (bh * LQ + qt * 128 + qw * 32) * 1024;
    const uint32_t* pV = g_vt + ((size_t)b * FF + ft * 256 + fw * 64) * LQ;

    float acc[2][8][4] = {};

#pragma unroll 2
    for (int kc = 0; kc < 64; kc++) {
        const int k0 = kc * 16 + tig * 2;
        uint32_t au[2][4];
#pragma unroll
        for (int mi = 0; mi < 2; mi++) {
            const float* ptr = pA + (size_t)(mi * 16 + g) * 1024 + k0;
            float2 e0 = *(const float2*)(ptr);
            float2 e1 = *(const float2*)(ptr + 8 * 1024);
            float2 e2 = *(const float2*)(ptr + 8);
            float2 e3 = *(const float2*)(ptr + 8 * 1024 + 8);
            __half2 t;
            t = __floats2half2_rn(e0.x * iv[mi][0], e0.y * iv[mi][0]); au[mi][0] = *(uint32_t*)&t;
            t = __floats2half2_rn(e1.x * iv[mi][1], e1.y * iv[mi][1]); au[mi][1] = *(uint32_t*)&t;
            t = __floats2half2_rn(e2.x * iv[mi][0], e2.y * iv[mi][0]); au[mi][2] = *(uint32_t*)&t;
            t = __floats2half2_rn(e3.x * iv[mi][1], e3.y * iv[mi][1]); au[mi][3] = *(uint32_t*)&t;
        }
#pragma unroll
        for (int ni = 0; ni < 8; ni++) {
            const uint32_t* vp = pV + (size_t)(ni * 8 + g) * 1024 + k0;
            uint2 v0 = *(const uint2*)(vp);
            uint2 v1 = *(const uint2*)(vp + 8);
            uint32_t b0h = __byte_perm(v0.x, v0.y, 0x5410);
            uint32_t b0l = __byte_perm(v0.x, v0.y, 0x7632);
            uint32_t b1h = __byte_perm(v1.x, v1.y, 0x5410);
            uint32_t b1l = __byte_perm(v1.x, v1.y, 0x7632);
#pragma unroll
            for (int mi = 0; mi < 2; mi++) {
                mma_f16(acc[mi][ni], au[mi][0], au[mi][1], au[mi][2], au[mi][3], b0h, b1h);
                mma_f16(acc[mi][ni], au[mi][0], au[mi][1], au[mi][2], au[mi][3], b0l, b1l);
            }
        }
    }

    // store O
#pragma unroll
    for (int mi = 0; mi < 2; mi++) {
        const int q0 = qt * 128 + qw * 32 + mi * 16 + g;
#pragma unroll
        for (int ni = 0; ni < 8; ni++) {
            const int f = ft * 256 + fw * 64 + ni * 8 + tig * 2;
            float* op0 = out + ((size_t)q0 * BB + b) * (HH * FF) + h * FF + f;
            float* op1 = out + ((size_t)(q0 + 8) * BB + b) * (HH * FF) + h * FF + f;
            *(float2*)op0 = make_float2(acc[mi][ni][0], acc[mi][ni][1]);
            *(float2*)op1 = make_float2(acc[mi][ni][2], acc[mi][ni][3]);
        }
    }
}

// ---------------------------------------------------------------------------
extern "C" void kernel_launch(void* const* d_in, const int* in_sizes, int n_in,
                              void* d_out, int out_size) {
    const float* query = (const float*)d_in[0];
    const float* key   = (const float*)d_in[1];
    const float* value = (const float*)d_in[2];
    const float* Wk    = (const float*)d_in[3];
    const float* bk    = (const float*)d_in[4];
    float* out = (float*)d_out;

    __nv_bfloat16 *q1, *q2, *q3, *k1, *k2, *k3;
    cudaGetSymbolAddress((void**)&q1, g_wq1);
    cudaGetSymbolAddress((void**)&q2, g_wq2);
    cudaGetSymbolAddress((void**)&q3, g_wq3);
    cudaGetSymbolAddress((void**)&k1, g_wk1);
    cudaGetSymbolAddress((void**)&k2, g_wk2);
    cudaGetSymbolAddress((void**)&k3, g_wk3);

    dim3 pg((LQ * BB) / 64, HH);
    proj_kernel<<<pg, 256>>>(query, Wk, bk, q1, q2, q3, TEMPS);
    proj_kernel<<<pg, 256>>>(key, Wk, bk, k1, k2, k3, 1.0f);

    dim3 vg(FF / 32, LQ / 32, BB);
    vsplit_kernel<<<vg, dim3(32, 8)>>>(value);

    dim3 sg(8 * 16, HH, BB);   // (128, 8, 16)
    scores_kernel<<<sg, 256>>>();

    dim3 ag((LQ / 128) * 2, HH, BB);  // (16, 8, 16)
    pv_kernel<<<ag, 512>>>(out);
}

// round 10
// speedup vs baseline: 2.5496x; 1.4925x over previous
#include <cuda_runtime.h>
#include <cuda_bf16.h>
#include <cuda_fp16.h>
#include <math.h>
#include <stdint.h>

#define LQ 1024
#define BB 16
#define FF 512
#define HH 8
#define KK 64
#define TEMPS 30.0f

// ------------------------- static scratch -------------------------
// split-bf16 parts of normalized projections, [b][h][l][64] k-contig
__device__ __align__(16) __nv_bfloat16 g_wq1[(size_t)BB * HH * LQ * KK];
__device__ __align__(16) __nv_bfloat16 g_wq2[(size_t)BB * HH * LQ * KK];
__device__ __align__(16) __nv_bfloat16 g_wq3[(size_t)BB * HH * LQ * KK];
__device__ __align__(16) __nv_bfloat16 g_wk1[(size_t)BB * HH * LQ * KK];
__device__ __align__(16) __nv_bfloat16 g_wk2[(size_t)BB * HH * LQ * KK];
__device__ __align__(16) __nv_bfloat16 g_wk3[(size_t)BB * HH * LQ * KK];
// V in B-fragment layout: [b][f8 0..63][s16 0..63][lane 0..31][b0h,b1h,b0l,b1l]
__device__ __align__(16) uint32_t g_vt[(size_t)BB * 64 * 64 * 32 * 4];
// exp(scores) in A-fragment layout:
// [bh][q16 0..63][s16 0..63][plane 0..1][lane 0..31][4 f32]
__device__ __align__(16) float g_S[(size_t)BB * HH * 64 * 64 * 2 * 32 * 4];
// row partial sums (32 partials of 32 cols per row)
__device__ __align__(16) float g_ps[(size_t)BB * HH * LQ * 32];

// ------------------------- helpers -------------------------
__device__ __forceinline__ void split3(float x, __nv_bfloat16& a, __nv_bfloat16& b, __nv_bfloat16& c) {
    a = __float2bfloat16(x);
    float r = x - __bfloat162float(a);
    b = __float2bfloat16(r);
    c = __float2bfloat16(r - __bfloat162float(b));
}

__device__ __forceinline__ void mma_bf16(float c[4], uint32_t a0, uint32_t a1, uint32_t a2,
                                         uint32_t a3, uint32_t b0, uint32_t b1) {
    asm("mma.sync.aligned.m16n8k16.row.col.f32.bf16.bf16.f32 "
        "{%0,%1,%2,%3}, {%4,%5,%6,%7}, {%8,%9}, {%0,%1,%2,%3};"
        : "+f"(c[0]), "+f"(c[1]), "+f"(c[2]), "+f"(c[3])
        : "r"(a0), "r"(a1), "r"(a2), "r"(a3), "r"(b0), "r"(b1));
}
__device__ __forceinline__ void mma_f16(float c[4], uint32_t a0, uint32_t a1, uint32_t a2,
                                        uint32_t a3, uint32_t b0, uint32_t b1) {
    asm("mma.sync.aligned.m16n8k16.row.col.f32.f16.f16.f32 "
        "{%0,%1,%2,%3}, {%4,%5,%6,%7}, {%8,%9}, {%0,%1,%2,%3};"
        : "+f"(c[0]), "+f"(c[1]), "+f"(c[2]), "+f"(c[3])
        : "r"(a0), "r"(a1), "r"(a2), "r"(a3), "r"(b0), "r"(b1));
}
__device__ __forceinline__ void ldsm4(uint32_t& r0, uint32_t& r1, uint32_t& r2, uint32_t& r3,
                                      uint32_t a) {
    asm volatile("ldmatrix.sync.aligned.m8n8.x4.shared.b16 {%0,%1,%2,%3}, [%4];"
                 : "=r"(r0), "=r"(r1), "=r"(r2), "=r"(r3) : "r"(a));
}
__device__ __forceinline__ uint32_t smem_u32(const void* p) {
    uint32_t a;
    asm("{ .reg .u64 t; cvta.to.shared.u64 t, %1; cvt.u32.u64 %0, t; }" : "=r"(a) : "l"(p));
    return a;
}
#define SWZ(o) ((o) ^ (((o) >> 3) & 0x70))

extern __shared__ __align__(1024) char smx[];

// ---------------------------------------------------------------------------
// Kernel 1: projection + bias + L2-normalize (SIMT fp32); writes 3-way
// split-bf16 parts. scale folds TEMP for Q. (unchanged, proven)
// ---------------------------------------------------------------------------
__global__ __launch_bounds__(256) void proj_kernel(const float* __restrict__ X,
                                                   const float* __restrict__ W,
                                                   const float* __restrict__ bias,
                                                   __nv_bfloat16* __restrict__ o1,
                                                   __nv_bfloat16* __restrict__ o2,
                                                   __nv_bfloat16* __restrict__ o3,
                                                   float scale) {
    __shared__ __align__(16) float As[16][68];
    __shared__ __align__(16) float Bs[16][68];
    __shared__ __align__(16) float Cs[64][68];
    __shared__ float scl[64];

    const int tid = threadIdx.x;
    const int tx = tid & 15, ty = tid >> 4;
    const int m0 = blockIdx.x * 64;
    const int h = blockIdx.y;
    const int n0 = h * 64;

    float acc[4][4] = {};
    const int lrow = tid >> 2;
    const int lk4 = (tid & 3) * 4;

    const float* Xp = X + (size_t)(m0 + lrow) * FF + lk4;
    const float* Wp = W + (size_t)(n0 + lrow) * FF + lk4;

    for (int k0 = 0; k0 < FF; k0 += 16) {
        float4 a = *(const float4*)(Xp + k0);
        float4 w = *(const float4*)(Wp + k0);
        As[lk4 + 0][lrow] = a.x; As[lk4 + 1][lrow] = a.y;
        As[lk4 + 2][lrow] = a.z; As[lk4 + 3][lrow] = a.w;
        Bs[lk4 + 0][lrow] = w.x; Bs[lk4 + 1][lrow] = w.y;
        Bs[lk4 + 2][lrow] = w.z; Bs[lk4 + 3][lrow] = w.w;
        __syncthreads();
#pragma unroll
        for (int k = 0; k < 16; k++) {
            float4 av = *(const float4*)&As[k][ty * 4];
            float4 bw = *(const float4*)&Bs[k][tx * 4];
            float aa[4] = {av.x, av.y, av.z, av.w};
            float ww[4] = {bw.x, bw.y, bw.z, bw.w};
#pragma unroll
            for (int i = 0; i < 4; i++)
#pragma unroll
                for (int j = 0; j < 4; j++)
                    acc[i][j] = fmaf(aa[i], ww[j], acc[i][j]);
        }
        __syncthreads();
    }

    float bj[4];
#pragma unroll
    for (int j = 0; j < 4; j++) bj[j] = bias[n0 + tx * 4 + j];
#pragma unroll
    for (int i = 0; i < 4; i++)
#pragma unroll
        for (int j = 0; j < 4; j++)
            Cs[ty * 4 + i][tx * 4 + j] = acc[i][j] + bj[j];
    __syncthreads();

    if (tid < 64) {
        float ss = 0.f;
#pragma unroll 8
        for (int c = 0; c < 64; c++) {
            float v = Cs[tid][c];
            ss = fmaf(v, v, ss);
        }
        scl[tid] = scale / fmaxf(sqrtf(ss), 1e-12f);
    }
    __syncthreads();

#pragma unroll
    for (int i = 0; i < 4; i++) {
        int m = m0 + ty * 4 + i;
        int q = m >> 4;
        int b = m & 15;
        float s = scl[ty * 4 + i];
        float v[4];
#pragma unroll
        for (int j = 0; j < 4; j++) v[j] = Cs[ty * 4 + i][tx * 4 + j] * s;
        __nv_bfloat16 p1[4], p2[4], p3[4];
#pragma unroll
        for (int j = 0; j < 4; j++) split3(v[j], p1[j], p2[j], p3[j]);
        size_t off = (((size_t)(b * HH + h) * LQ + q) * KK) + tx * 4;
        __nv_bfloat162 t;
        t = __halves2bfloat162(p1[0], p1[1]); *(uint32_t*)(o1 + off)     = *(uint32_t*)&t;
        t = __halves2bfloat162(p1[2], p1[3]); *(uint32_t*)(o1 + off + 2) = *(uint32_t*)&t;
        t = __halves2bfloat162(p2[0], p2[1]); *(uint32_t*)(o2 + off)     = *(uint32_t*)&t;
        t = __halves2bfloat162(p2[2], p2[3]); *(uint32_t*)(o2 + off + 2) = *(uint32_t*)&t;
        t = __halves2bfloat162(p3[0], p3[1]); *(uint32_t*)(o3 + off)     = *(uint32_t*)&t;
        t = __halves2bfloat162(p3[2], p3[3]); *(uint32_t*)(o3 + off + 2) = *(uint32_t*)&t;
    }
}

// ---------------------------------------------------------------------------
// Kernel 2: V -> B-fragment layout, fp16 hi/lo packed per lane.
// grid (16 f-tiles, 32 s-tiles, 16 b), 256 thr. Tile = 32f x 32s.
// ---------------------------------------------------------------------------
__global__ __launch_bounds__(256) void vsplit_kernel(const float* __restrict__ value) {
    __shared__ float t[32][33];   // [s][f]
    const int tid = threadIdx.x;
    const int f0 = blockIdx.x * 32, s0 = blockIdx.y * 32, b = blockIdx.z;

    for (int u = tid; u < 1024; u += 256) {
        int s = u >> 5, f = u & 31;
        t[s][f] = value[(size_t)(s0 + s) * (BB * FF) + b * FF + f0 + f];
    }
    __syncthreads();

    // 8 fragment blocks: blk = sb*4 + fb (sb<2 s16-blocks, fb<4 f8-blocks)
    const int blk = tid >> 5, lane = tid & 31;
    const int sb = blk >> 2, fb = blk & 3;
    const int g = lane >> 2, tig = lane & 3;
    const int s_l = sb * 16 + tig * 2;
    const int f_l = fb * 8 + g;
    float v0 = t[s_l][f_l], v1 = t[s_l + 1][f_l];
    float v2 = t[s_l + 8][f_l], v3 = t[s_l + 9][f_l];
    __half h0 = __float2half_rn(v0), h1 = __float2half_rn(v1);
    __half h2v = __float2half_rn(v2), h3 = __float2half_rn(v3);
    __half l0 = __float2half_rn(v0 - __half2float(h0));
    __half l1 = __float2half_rn(v1 - __half2float(h1));
    __half l2 = __float2half_rn(v2 - __half2float(h2v));
    __half l3 = __float2half_rn(v3 - __half2float(h3));
    __half2 bh0 = __halves2half2(h0, h1), bh1 = __halves2half2(h2v, h3);
    __half2 bl0 = __halves2half2(l0, l1), bl1 = __halves2half2(l2, l3);
    uint4 u;
    u.x = *(uint32_t*)&bh0; u.y = *(uint32_t*)&bh1;
    u.z = *(uint32_t*)&bl0; u.w = *(uint32_t*)&bl1;
    const int f8 = (f0 >> 3) + fb;       // 0..63
    const int s16 = (s0 >> 4) + sb;      // 0..63
    ((uint4*)g_vt)[(((size_t)b * 64 + f8) * 64 + s16) * 32 + lane] = u;
}

// ---------------------------------------------------------------------------
// Kernel 3: scores. CTA (qt 128q, nt 64n, h, b); 256 thr, 8 warps = 4qw x 2nw;
// warp = 32q x 32n. smem-staged wq/wk (SW128) + ldmatrix. 6 split-bf16 passes.
// Epilogue: exp, partial row sums, A-fragment-layout store of exp(S).
// ---------------------------------------------------------------------------
#define AQ(p) ((p) * 16384)
#define BK(p) (49152 + (p) * 8192)
#define SCORES_SMEM 73728

__global__ __launch_bounds__(256) void scores_kernel() {
    const uint32_t sb = smem_u32(smx);
    const int tid = threadIdx.x;
    const int w = tid >> 5, lane = tid & 31;
    const int g = lane >> 2, tig = lane & 3;
    const int qw = w >> 1, nw = w & 1;
    const int qt = blockIdx.x >> 4, nt = blockIdx.x & 15;
    const int h = blockIdx.y, b = blockIdx.z;
    const size_t bh = (size_t)(b * HH + h);

    // stage wq (128 x 64) x3 parts and wk (64 x 64) x3 parts, SW128 swizzled
    {
        const __nv_bfloat16* Asrc[3] = {
            g_wq1 + (bh * LQ + (size_t)qt * 128) * KK,
            g_wq2 + (bh * LQ + (size_t)qt * 128) * KK,
            g_wq3 + (bh * LQ + (size_t)qt * 128) * KK};
        for (int u = tid; u < 1024; u += 256) {
            int r = u >> 3, c = u & 7;
            uint32_t d = SWZ((uint32_t)(r * 128 + c * 16));
#pragma unroll
            for (int p = 0; p < 3; p++)
                *(uint4*)(smx + AQ(p) + d) = *(const uint4*)(Asrc[p] + r * 64 + c * 8);
        }
        const __nv_bfloat16* Bsrc[3] = {
            g_wk1 + (bh * LQ + (size_t)nt * 64) * KK,
            g_wk2 + (bh * LQ + (size_t)nt * 64) * KK,
            g_wk3 + (bh * LQ + (size_t)nt * 64) * KK};
        for (int u = tid; u < 512; u += 256) {
            int r = u >> 3, c = u & 7;
            uint32_t d = SWZ((uint32_t)(r * 128 + c * 16));
#pragma unroll
            for (int p = 0; p < 3; p++)
                *(uint4*)(smx + BK(p) + d) = *(const uint4*)(Bsrc[p] + r * 64 + c * 8);
        }
    }
    __syncthreads();

    float acc[2][4][4] = {};

    const int mat = lane >> 3, rin = lane & 7;
    // A lane addressing: row' = (mat&1)*8 + rin, khalf = mat>>1
    // B lane addressing: row' = (mat>>1)*8 + rin, khalf = mat&1
    const int arow = (mat & 1) * 8 + rin, akh = mat >> 1;
    const int brow = (mat >> 1) * 8 + rin, bkh = mat & 1;

#pragma unroll
    for (int kc = 0; kc < 4; kc++) {
        uint32_t A[3][2][4], Bf[3][2][4];
#pragma unroll
        for (int p = 0; p < 3; p++) {
#pragma unroll
            for (int mi = 0; mi < 2; mi++) {
                uint32_t a = sb + AQ(p) +
                    SWZ((uint32_t)((qw * 32 + mi * 16 + arow) * 128 + kc * 32 + akh * 16));
                ldsm4(A[p][mi][0], A[p][mi][1], A[p][mi][2], A[p][mi][3], a);
            }
#pragma unroll
            for (int j = 0; j < 2; j++) {
                uint32_t a = sb + BK(p) +
                    SWZ((uint32_t)((nw * 32 + j * 16 + brow) * 128 + kc * 32 + bkh * 16));
                ldsm4(Bf[p][j][0], Bf[p][j][1], Bf[p][j][2], Bf[p][j][3], a);
            }
        }
        const int pa[6] = {0, 0, 1, 1, 0, 2};
        const int pb[6] = {0, 1, 0, 1, 2, 0};
#pragma unroll
        for (int p = 0; p < 6; p++)
#pragma unroll
            for (int mi = 0; mi < 2; mi++)
#pragma unroll
                for (int j = 0; j < 2; j++) {
                    mma_bf16(acc[mi][2 * j], A[pa[p]][mi][0], A[pa[p]][mi][1],
                             A[pa[p]][mi][2], A[pa[p]][mi][3], Bf[pb[p]][j][0], Bf[pb[p]][j][1]);
                    mma_bf16(acc[mi][2 * j + 1], A[pa[p]][mi][0], A[pa[p]][mi][1],
                             A[pa[p]][mi][2], A[pa[p]][mi][3], Bf[pb[p]][j][2], Bf[pb[p]][j][3]);
                }
    }

    // epilogue: exp + fragment-layout store + per-32col partial row sums
#pragma unroll
    for (int mi = 0; mi < 2; mi++) {
        const int q16 = qt * 8 + qw * 2 + mi;
        float e[4][4];
        float sum0 = 0.f, sum1 = 0.f;
#pragma unroll
        for (int ni = 0; ni < 4; ni++) {
            e[ni][0] = __expf(acc[mi][ni][0]);
            e[ni][1] = __expf(acc[mi][ni][1]);
            e[ni][2] = __expf(acc[mi][ni][2]);
            e[ni][3] = __expf(acc[mi][ni][3]);
            sum0 += e[ni][0] + e[ni][1];
            sum1 += e[ni][2] + e[ni][3];
        }
#pragma unroll
        for (int j = 0; j < 2; j++) {
            const int s16 = nt * 4 + nw * 2 + j;
            float4* dst = (float4*)(g_S + ((((size_t)bh * 64 + q16) * 64 + s16) * 2) * 128) + lane;
            dst[0]  = make_float4(e[2 * j][0], e[2 * j][1], e[2 * j + 1][0], e[2 * j + 1][1]);
            dst[32] = make_float4(e[2 * j][2], e[2 * j][3], e[2 * j + 1][2], e[2 * j + 1][3]);
        }
        sum0 += __shfl_xor_sync(0xFFFFFFFFu, sum0, 1);
        sum0 += __shfl_xor_sync(0xFFFFFFFFu, sum0, 2);
        sum1 += __shfl_xor_sync(0xFFFFFFFFu, sum1, 1);
        sum1 += __shfl_xor_sync(0xFFFFFFFFu, sum1, 2);
        if (tig == 0) {
            const int row0 = q16 * 16 + g;
            const int pidx = nt * 2 + nw;
            g_ps[(bh * LQ + row0) * 32 + pidx] = sum0;
            g_ps[(bh * LQ + row0 + 8) * 32 + pidx] = sum1;
        }
    }
}

// ---------------------------------------------------------------------------
// Kernel 4: P@V. CTA (qt 128q, ft 256f, h, b); 512 thr; warp = 32q x 64f.
// All operands loaded as ready-made fragments (coalesced LDG.128), no smem.
// ---------------------------------------------------------------------------
__global__ __launch_bounds__(512) void pv_kernel(float* __restrict__ out) {
    __shared__ float sm_iv[128];
    const int tid = threadIdx.x;
    const int w = tid >> 5, lane = tid & 31;
    const int g = lane >> 2, tig = lane & 3;
    const int qw = w & 3, fw = w >> 2;
    const int qt = blockIdx.x >> 1, ft = blockIdx.x & 1;
    const int h = blockIdx.y, b = blockIdx.z;
    const size_t bh = (size_t)(b * HH + h);

    if (tid < 128) {
        const float4* pp = (const float4*)(g_ps + (bh * LQ + (size_t)qt * 128 + tid) * 32);
        float s = 0.f;
#pragma unroll
        for (int i = 0; i < 8; i++) {
            float4 v = pp[i];
            s += v.x + v.y + v.z + v.w;
        }
        sm_iv[tid] = 1.0f / s;
    }
    __syncthreads();

    float iv[2][2];
#pragma unroll
    for (int mi = 0; mi < 2; mi++) {
        iv[mi][0] = sm_iv[qw * 32 + mi * 16 + g];
        iv[mi][1] = sm_iv[qw * 32 + mi * 16 + g + 8];
    }

    // A fragment bases (per mi): [bh][q16][kc][plane][lane][4 f32]
    const float4* Abase[2];
#pragma unroll
    for (int mi = 0; mi < 2; mi++)
        Abase[mi] = (const float4*)(g_S +
            (((size_t)bh * 64 + qt * 8 + qw * 2 + mi) * 64) * 256) + lane;

    float acc[2][8][4] = {};

#pragma unroll 2
    for (int kc = 0; kc < 64; kc++) {
        uint32_t au[2][4];
#pragma unroll
        for (int mi = 0; mi < 2; mi++) {
            float4 f0 = Abase[mi][kc * 64];        // plane 0: a0,a2
            float4 f1 = Abase[mi][kc * 64 + 32];   // plane 1: a1,a3
            __half2 t;
            t = __floats2half2_rn(f0.x * iv[mi][0], f0.y * iv[mi][0]); au[mi][0] = *(uint32_t*)&t;
            t = __floats2half2_rn(f1.x * iv[mi][1], f1.y * iv[mi][1]); au[mi][1] = *(uint32_t*)&t;
            t = __floats2half2_rn(f0.z * iv[mi][0], f0.w * iv[mi][0]); au[mi][2] = *(uint32_t*)&t;
            t = __floats2half2_rn(f1.z * iv[mi][1], f1.w * iv[mi][1]); au[mi][3] = *(uint32_t*)&t;
        }
#pragma unroll
        for (int ni = 0; ni < 8; ni++) {
            const int f8 = ft * 32 + fw * 8 + ni;
            uint4 v = ((const uint4*)g_vt)[(((size_t)b * 64 + f8) * 64 + kc) * 32 + lane];
#pragma unroll
            for (int mi = 0; mi < 2; mi++) {
                mma_f16(acc[mi][ni], au[mi][0], au[mi][1], au[mi][2], au[mi][3], v.x, v.y);
                mma_f16(acc[mi][ni], au[mi][0], au[mi][1], au[mi][2], au[mi][3], v.z, v.w);
            }
        }
    }

    // store O
#pragma unroll
    for (int mi = 0; mi < 2; mi++) {
        const int q0 = qt * 128 + qw * 32 + mi * 16 + g;
#pragma unroll
        for (int ni = 0; ni < 8; ni++) {
            const int f = ft * 256 + fw * 64 + ni * 8 + tig * 2;
            float* op0 = out + ((size_t)q0 * BB + b) * (HH * FF) + h * FF + f;
            float* op1 = out + ((size_t)(q0 + 8) * BB + b) * (HH * FF) + h * FF + f;
            *(float2*)op0 = make_float2(acc[mi][ni][0], acc[mi][ni][1]);
            *(float2*)op1 = make_float2(acc[mi][ni][2], acc[mi][ni][3]);
        }
    }
}

// ---------------------------------------------------------------------------
extern "C" void kernel_launch(void* const* d_in, const int* in_sizes, int n_in,
                              void* d_out, int out_size) {
    const float* query = (const float*)d_in[0];
    const float* key   = (const float*)d_in[1];
    const float* value = (const float*)d_in[2];
    const float* Wk    = (const float*)d_in[3];
    const float* bk    = (const float*)d_in[4];
    float* out = (float*)d_out;

    __nv_bfloat16 *q1, *q2, *q3, *k1, *k2, *k3;
    cudaGetSymbolAddress((void**)&q1, g_wq1);
    cudaGetSymbolAddress((void**)&q2, g_wq2);
    cudaGetSymbolAddress((void**)&q3, g_wq3);
    cudaGetSymbolAddress((void**)&k1, g_wk1);
    cudaGetSymbolAddress((void**)&k2, g_wk2);
    cudaGetSymbolAddress((void**)&k3, g_wk3);

    dim3 pg((LQ * BB) / 64, HH);
    proj_kernel<<<pg, 256>>>(query, Wk, bk, q1, q2, q3, TEMPS);
    proj_kernel<<<pg, 256>>>(key, Wk, bk, k1, k2, k3, 1.0f);

    dim3 vg(FF / 32, LQ / 32, BB);
    vsplit_kernel<<<vg, 256>>>(value);

    cudaFuncSetAttribute(scores_kernel, cudaFuncAttributeMaxDynamicSharedMemorySize, SCORES_SMEM);
    dim3 sg(8 * 16, HH, BB);   // qt*16+nt = 128, h 8, b 16
    scores_kernel<<<sg, 256, SCORES_SMEM>>>();

    dim3 ag((LQ / 128) * 2, HH, BB);  // (16, 8, 16)
    pv_kernel<<<ag, 512>>>(out);
}

// round 11
// speedup vs baseline: 3.1454x; 1.2337x over previous
#include <cuda_runtime.h>
#include <cuda_bf16.h>
#include <cuda_fp16.h>
#include <math.h>
#include <stdint.h>

#define LQ 1024
#define BB 16
#define FF 512
#define HH 8
#define KK 64
#define TEMPS 30.0f

// ------------------------- static scratch -------------------------
__device__ __align__(16) __nv_bfloat16 g_wq1[(size_t)BB * HH * LQ * KK];
__device__ __align__(16) __nv_bfloat16 g_wq2[(size_t)BB * HH * LQ * KK];
__device__ __align__(16) __nv_bfloat16 g_wq3[(size_t)BB * HH * LQ * KK];
__device__ __align__(16) __nv_bfloat16 g_wk1[(size_t)BB * HH * LQ * KK];
__device__ __align__(16) __nv_bfloat16 g_wk2[(size_t)BB * HH * LQ * KK];
__device__ __align__(16) __nv_bfloat16 g_wk3[(size_t)BB * HH * LQ * KK];
// V (hi-only fp16) in B-fragment layout: [b][f8 0..63][s16 0..63][lane][b0h,b1h]
__device__ __align__(16) uint32_t g_vt[(size_t)BB * 64 * 64 * 32 * 2];
// exp(scores) in A-fragment layout: [bh][q16][s16][plane 0..1][lane][4 f32]
__device__ __align__(16) float g_S[(size_t)BB * HH * 64 * 64 * 2 * 32 * 4];
// row partial sums (32 partials of 32 cols per row)
__device__ __align__(16) float g_ps[(size_t)BB * HH * LQ * 32];

// ------------------------- helpers -------------------------
__device__ __forceinline__ void split3(float x, __nv_bfloat16& a, __nv_bfloat16& b, __nv_bfloat16& c) {
    a = __float2bfloat16(x);
    float r = x - __bfloat162float(a);
    b = __float2bfloat16(r);
    c = __float2bfloat16(r - __bfloat162float(b));
}
__device__ __forceinline__ void mma_bf16(float c[4], uint32_t a0, uint32_t a1, uint32_t a2,
                                         uint32_t a3, uint32_t b0, uint32_t b1) {
    asm("mma.sync.aligned.m16n8k16.row.col.f32.bf16.bf16.f32 "
        "{%0,%1,%2,%3}, {%4,%5,%6,%7}, {%8,%9}, {%0,%1,%2,%3};"
        : "+f"(c[0]), "+f"(c[1]), "+f"(c[2]), "+f"(c[3])
        : "r"(a0), "r"(a1), "r"(a2), "r"(a3), "r"(b0), "r"(b1));
}
__device__ __forceinline__ void mma_f16(float c[4], uint32_t a0, uint32_t a1, uint32_t a2,
                                        uint32_t a3, uint32_t b0, uint32_t b1) {
    asm("mma.sync.aligned.m16n8k16.row.col.f32.f16.f16.f32 "
        "{%0,%1,%2,%3}, {%4,%5,%6,%7}, {%8,%9}, {%0,%1,%2,%3};"
        : "+f"(c[0]), "+f"(c[1]), "+f"(c[2]), "+f"(c[3])
        : "r"(a0), "r"(a1), "r"(a2), "r"(a3), "r"(b0), "r"(b1));
}
__device__ __forceinline__ void ldsm4(uint32_t& r0, uint32_t& r1, uint32_t& r2, uint32_t& r3,
                                      uint32_t a) {
    asm volatile("ldmatrix.sync.aligned.m8n8.x4.shared.b16 {%0,%1,%2,%3}, [%4];"
                 : "=r"(r0), "=r"(r1), "=r"(r2), "=r"(r3) : "r"(a));
}
__device__ __forceinline__ uint32_t smem_u32(const void* p) {
    uint32_t a;
    asm("{ .reg .u64 t; cvta.to.shared.u64 t, %1; cvt.u32.u64 %0, t; }" : "=r"(a) : "l"(p));
    return a;
}
#define SWZ(o) ((o) ^ (((o) >> 3) & 0x70))

extern __shared__ __align__(1024) char smx[];

// pack 8 floats' split parts into 3 uint4 and store
__device__ __forceinline__ void split_store8(const float* v, char* d1, char* d2, char* d3) {
    __nv_bfloat16 p1[8], p2[8], p3[8];
#pragma unroll
    for (int e = 0; e < 8; e++) split3(v[e], p1[e], p2[e], p3[e]);
    uint4 u1, u2, u3;
#pragma unroll
    for (int e = 0; e < 4; e++) {
        __nv_bfloat162 t;
        t = __halves2bfloat162(p1[2 * e], p1[2 * e + 1]); ((uint32_t*)&u1)[e] = *(uint32_t*)&t;
        t = __halves2bfloat162(p2[2 * e], p2[2 * e + 1]); ((uint32_t*)&u2)[e] = *(uint32_t*)&t;
        t = __halves2bfloat162(p3[2 * e], p3[2 * e + 1]); ((uint32_t*)&u3)[e] = *(uint32_t*)&t;
    }
    *(uint4*)d1 = u1; *(uint4*)d2 = u2; *(uint4*)d3 = u3;
}

// ---------------------------------------------------------------------------
// Kernel 1: projection via split-bf16 mma. CTA = 128m x 64n (one head),
// K=512 in 8 staged chunks of 64. Epilogue: +bias, L2-normalize, split3 out.
// ---------------------------------------------------------------------------
#define PA(p) ((p) * 16384)
#define PB(p) (49152 + (p) * 8192)
#define PROJ_SMEM 73728

__global__ __launch_bounds__(256) void projmma_kernel(const float* __restrict__ X,
                                                      const float* __restrict__ W,
                                                      const float* __restrict__ bias,
                                                      __nv_bfloat16* __restrict__ o1,
                                                      __nv_bfloat16* __restrict__ o2,
                                                      __nv_bfloat16* __restrict__ o3,
                                                      float scale) {
    __shared__ float ssq[128][2];
    const uint32_t sb = smem_u32(smx);
    const int tid = threadIdx.x;
    const int w = tid >> 5, lane = tid & 31;
    const int g = lane >> 2, tig = lane & 3;
    const int qw = w >> 1, nw = w & 1;
    const int m0 = blockIdx.x * 128;
    const int h = blockIdx.y;
    const int n0 = h * 64;

    const int mat = lane >> 3, rin = lane & 7;
    const int arow = (mat & 1) * 8 + rin, akh = mat >> 1;
    const int brow = (mat >> 1) * 8 + rin, bkh = mat & 1;

    float acc[2][4][4] = {};

    for (int kc64 = 0; kc64 < 8; kc64++) {
        // stage A: 128 x 64 f32 -> 3 bf16 tiles (SW128)
        {
            const int r = tid >> 1, half = tid & 1;
            const float4* src = (const float4*)(X + (size_t)(m0 + r) * FF + kc64 * 64 + half * 32);
#pragma unroll
            for (int j = 0; j < 4; j++) {
                float4 fa = src[2 * j], fb = src[2 * j + 1];
                float v[8] = {fa.x, fa.y, fa.z, fa.w, fb.x, fb.y, fb.z, fb.w};
                uint32_t d = SWZ((uint32_t)(r * 128 + half * 64 + j * 16));
                split_store8(v, smx + PA(0) + d, smx + PA(1) + d, smx + PA(2) + d);
            }
        }
        // stage B: 64 x 64 f32 -> 3 bf16 tiles
        {
            const int r = tid >> 2, q4 = tid & 3;
            const float4* src = (const float4*)(W + (size_t)(n0 + r) * FF + kc64 * 64 + q4 * 16);
#pragma unroll
            for (int j = 0; j < 2; j++) {
                float4 fa = src[2 * j], fb = src[2 * j + 1];
                float v[8] = {fa.x, fa.y, fa.z, fa.w, fb.x, fb.y, fb.z, fb.w};
                uint32_t d = SWZ((uint32_t)(r * 128 + q4 * 32 + j * 16));
                split_store8(v, smx + PB(0) + d, smx + PB(1) + d, smx + PB(2) + d);
            }
        }
        __syncthreads();

#pragma unroll
        for (int kc = 0; kc < 4; kc++) {
            uint32_t A[3][2][4], Bf[3][2][4];
#pragma unroll
            for (int p = 0; p < 3; p++) {
#pragma unroll
                for (int mi = 0; mi < 2; mi++) {
                    uint32_t a = sb + PA(p) +
                        SWZ((uint32_t)((qw * 32 + mi * 16 + arow) * 128 + kc * 32 + akh * 16));
                    ldsm4(A[p][mi][0], A[p][mi][1], A[p][mi][2], A[p][mi][3], a);
                }
#pragma unroll
                for (int j = 0; j < 2; j++) {
                    uint32_t a = sb + PB(p) +
                        SWZ((uint32_t)((nw * 32 + j * 16 + brow) * 128 + kc * 32 + bkh * 16));
                    ldsm4(Bf[p][j][0], Bf[p][j][1], Bf[p][j][2], Bf[p][j][3], a);
                }
            }
            const int pa[6] = {0, 0, 1, 1, 0, 2};
            const int pb[6] = {0, 1, 0, 1, 2, 0};
#pragma unroll
            for (int p = 0; p < 6; p++)
#pragma unroll
                for (int mi = 0; mi < 2; mi++)
#pragma unroll
                    for (int j = 0; j < 2; j++) {
                        mma_bf16(acc[mi][2 * j], A[pa[p]][mi][0], A[pa[p]][mi][1],
                                 A[pa[p]][mi][2], A[pa[p]][mi][3], Bf[pb[p]][j][0], Bf[pb[p]][j][1]);
                        mma_bf16(acc[mi][2 * j + 1], A[pa[p]][mi][0], A[pa[p]][mi][1],
                                 A[pa[p]][mi][2], A[pa[p]][mi][3], Bf[pb[p]][j][2], Bf[pb[p]][j][3]);
                    }
        }
        __syncthreads();
    }

    // bias
    float2 bb[4];
#pragma unroll
    for (int ni = 0; ni < 4; ni++) {
        bb[ni] = *(const float2*)(bias + n0 + nw * 32 + ni * 8 + tig * 2);
#pragma unroll
        for (int mi = 0; mi < 2; mi++) {
            acc[mi][ni][0] += bb[ni].x; acc[mi][ni][1] += bb[ni].y;
            acc[mi][ni][2] += bb[ni].x; acc[mi][ni][3] += bb[ni].y;
        }
    }

    // ssq partial (over this warp's 32 cols), reduce over tig, cross-nw via smem
#pragma unroll
    for (int mi = 0; mi < 2; mi++) {
        float s0 = 0.f, s1 = 0.f;
#pragma unroll
        for (int ni = 0; ni < 4; ni++) {
            s0 = fmaf(acc[mi][ni][0], acc[mi][ni][0], s0);
            s0 = fmaf(acc[mi][ni][1], acc[mi][ni][1], s0);
            s1 = fmaf(acc[mi][ni][2], acc[mi][ni][2], s1);
            s1 = fmaf(acc[mi][ni][3], acc[mi][ni][3], s1);
        }
        s0 += __shfl_xor_sync(0xFFFFFFFFu, s0, 1);
        s0 += __shfl_xor_sync(0xFFFFFFFFu, s0, 2);
        s1 += __shfl_xor_sync(0xFFFFFFFFu, s1, 1);
        s1 += __shfl_xor_sync(0xFFFFFFFFu, s1, 2);
        if (tig == 0) {
            ssq[qw * 32 + mi * 16 + g][nw] = s0;
            ssq[qw * 32 + mi * 16 + g + 8][nw] = s1;
        }
    }
    __syncthreads();

#pragma unroll
    for (int mi = 0; mi < 2; mi++) {
        const int rg = qw * 32 + mi * 16 + g;
        float sc0 = scale / fmaxf(sqrtf(ssq[rg][0] + ssq[rg][1]), 1e-12f);
        float sc1 = scale / fmaxf(sqrtf(ssq[rg + 8][0] + ssq[rg + 8][1]), 1e-12f);
        const int m_0 = m0 + rg, m_1 = m0 + rg + 8;
        const size_t off0 = (((size_t)((m_0 & 15) * HH + h) * LQ + (m_0 >> 4)) * KK);
        const size_t off1 = (((size_t)((m_1 & 15) * HH + h) * LQ + (m_1 >> 4)) * KK);
#pragma unroll
        for (int ni = 0; ni < 4; ni++) {
            const int kl = nw * 32 + ni * 8 + tig * 2;
            __nv_bfloat16 a1[2], a2[2], a3[2];
            split3(acc[mi][ni][0] * sc0, a1[0], a2[0], a3[0]);
            split3(acc[mi][ni][1] * sc0, a1[1], a2[1], a3[1]);
            __nv_bfloat162 t;
            t = __halves2bfloat162(a1[0], a1[1]); *(uint32_t*)(o1 + off0 + kl) = *(uint32_t*)&t;
            t = __halves2bfloat162(a2[0], a2[1]); *(uint32_t*)(o2 + off0 + kl) = *(uint32_t*)&t;
            t = __halves2bfloat162(a3[0], a3[1]); *(uint32_t*)(o3 + off0 + kl) = *(uint32_t*)&t;
            split3(acc[mi][ni][2] * sc1, a1[0], a2[0], a3[0]);
            split3(acc[mi][ni][3] * sc1, a1[1], a2[1], a3[1]);
            t = __halves2bfloat162(a1[0], a1[1]); *(uint32_t*)(o1 + off1 + kl) = *(uint32_t*)&t;
            t = __halves2bfloat162(a2[0], a2[1]); *(uint32_t*)(o2 + off1 + kl) = *(uint32_t*)&t;
            t = __halves2bfloat162(a3[0], a3[1]); *(uint32_t*)(o3 + off1 + kl) = *(uint32_t*)&t;
        }
    }
}

// ---------------------------------------------------------------------------
// Kernel 2: V -> B-fragment layout, fp16 hi only, packed per lane.
// ---------------------------------------------------------------------------
__global__ __launch_bounds__(256) void vsplit_kernel(const float* __restrict__ value) {
    __shared__ float t[32][33];   // [s][f]
    const int tid = threadIdx.x;
    const int f0 = blockIdx.x * 32, s0 = blockIdx.y * 32, b = blockIdx.z;

    for (int u = tid; u < 1024; u += 256) {
        int s = u >> 5, f = u & 31;
        t[s][f] = value[(size_t)(s0 + s) * (BB * FF) + b * FF + f0 + f];
    }
    __syncthreads();

    const int blk = tid >> 5, lane = tid & 31;
    const int sbk = blk >> 2, fb = blk & 3;
    const int g = lane >> 2, tig = lane & 3;
    const int s_l = sbk * 16 + tig * 2;
    const int f_l = fb * 8 + g;
    __half2 bh0 = __floats2half2_rn(t[s_l][f_l], t[s_l + 1][f_l]);
    __half2 bh1 = __floats2half2_rn(t[s_l + 8][f_l], t[s_l + 9][f_l]);
    uint2 u;
    u.x = *(uint32_t*)&bh0; u.y = *(uint32_t*)&bh1;
    const int f8 = (f0 >> 3) + fb;
    const int s16 = (s0 >> 4) + sbk;
    ((uint2*)g_vt)[(((size_t)b * 64 + f8) * 64 + s16) * 32 + lane] = u;
}

// ---------------------------------------------------------------------------
// Kernel 3: scores (unchanged from round 10 win).
// ---------------------------------------------------------------------------
#define AQ(p) ((p) * 16384)
#define BK(p) (49152 + (p) * 8192)
#define SCORES_SMEM 73728

__global__ __launch_bounds__(256) void scores_kernel() {
    const uint32_t sb = smem_u32(smx);
    const int tid = threadIdx.x;
    const int w = tid >> 5, lane = tid & 31;
    const int g = lane >> 2, tig = lane & 3;
    const int qw = w >> 1, nw = w & 1;
    const int qt = blockIdx.x >> 4, nt = blockIdx.x & 15;
    const int h = blockIdx.y, b = blockIdx.z;
    const size_t bh = (size_t)(b * HH + h);

    {
        const __nv_bfloat16* Asrc[3] = {
            g_wq1 + (bh * LQ + (size_t)qt * 128) * KK,
            g_wq2 + (bh * LQ + (size_t)qt * 128) * KK,
            g_wq3 + (bh * LQ + (size_t)qt * 128) * KK};
        for (int u = tid; u < 1024; u += 256) {
            int r = u >> 3, c = u & 7;
            uint32_t d = SWZ((uint32_t)(r * 128 + c * 16));
#pragma unroll
            for (int p = 0; p < 3; p++)
                *(uint4*)(smx + AQ(p) + d) = *(const uint4*)(Asrc[p] + r * 64 + c * 8);
        }
        const __nv_bfloat16* Bsrc[3] = {
            g_wk1 + (bh * LQ + (size_t)nt * 64) * KK,
            g_wk2 + (bh * LQ + (size_t)nt * 64) * KK,
            g_wk3 + (bh * LQ + (size_t)nt * 64) * KK};
        for (int u = tid; u < 512; u += 256) {
            int r = u >> 3, c = u & 7;
            uint32_t d = SWZ((uint32_t)(r * 128 + c * 16));
#pragma unroll
            for (int p = 0; p < 3; p++)
                *(uint4*)(smx + BK(p) + d) = *(const uint4*)(Bsrc[p] + r * 64 + c * 8);
        }
    }
    __syncthreads();

    float acc[2][4][4] = {};
    const int mat = lane >> 3, rin = lane & 7;
    const int arow = (mat & 1) * 8 + rin, akh = mat >> 1;
    const int brow = (mat >> 1) * 8 + rin, bkh = mat & 1;

#pragma unroll
    for (int kc = 0; kc < 4; kc++) {
        uint32_t A[3][2][4], Bf[3][2][4];
#pragma unroll
        for (int p = 0; p < 3; p++) {
#pragma unroll
            for (int mi = 0; mi < 2; mi++) {
                uint32_t a = sb + AQ(p) +
                    SWZ((uint32_t)((qw * 32 + mi * 16 + arow) * 128 + kc * 32 + akh * 16));
                ldsm4(A[p][mi][0], A[p][mi][1], A[p][mi][2], A[p][mi][3], a);
            }
#pragma unroll
            for (int j = 0; j < 2; j++) {
                uint32_t a = sb + BK(p) +
                    SWZ((uint32_t)((nw * 32 + j * 16 + brow) * 128 + kc * 32 + bkh * 16));
                ldsm4(Bf[p][j][0], Bf[p][j][1], Bf[p][j][2], Bf[p][j][3], a);
            }
        }
        const int pa[6] = {0, 0, 1, 1, 0, 2};
        const int pb[6] = {0, 1, 0, 1, 2, 0};
#pragma unroll
        for (int p = 0; p < 6; p++)
#pragma unroll
            for (int mi = 0; mi < 2; mi++)
#pragma unroll
                for (int j = 0; j < 2; j++) {
                    mma_bf16(acc[mi][2 * j], A[pa[p]][mi][0], A[pa[p]][mi][1],
                             A[pa[p]][mi][2], A[pa[p]][mi][3], Bf[pb[p]][j][0], Bf[pb[p]][j][1]);
                    mma_bf16(acc[mi][2 * j + 1], A[pa[p]][mi][0], A[pa[p]][mi][1],
                             A[pa[p]][mi][2], A[pa[p]][mi][3], Bf[pb[p]][j][2], Bf[pb[p]][j][3]);
                }
    }

#pragma unroll
    for (int mi = 0; mi < 2; mi++) {
        const int q16 = qt * 8 + qw * 2 + mi;
        float e[4][4];
        float sum0 = 0.f, sum1 = 0.f;
#pragma unroll
        for (int ni = 0; ni < 4; ni++) {
            e[ni][0] = __expf(acc[mi][ni][0]);
            e[ni][1] = __expf(acc[mi][ni][1]);
            e[ni][2] = __expf(acc[mi][ni][2]);
            e[ni][3] = __expf(acc[mi][ni][3]);
            sum0 += e[ni][0] + e[ni][1];
            sum1 += e[ni][2] + e[ni][3];
        }
#pragma unroll
        for (int j = 0; j < 2; j++) {
            const int s16 = nt * 4 + nw * 2 + j;
            float4* dst = (float4*)(g_S + ((((size_t)bh * 64 + q16) * 64 + s16) * 2) * 128) + lane;
            dst[0]  = make_float4(e[2 * j][0], e[2 * j][1], e[2 * j + 1][0], e[2 * j + 1][1]);
            dst[32] = make_float4(e[2 * j][2], e[2 * j][3], e[2 * j + 1][2], e[2 * j + 1][3]);
        }
        sum0 += __shfl_xor_sync(0xFFFFFFFFu, sum0, 1);
        sum0 += __shfl_xor_sync(0xFFFFFFFFu, sum0, 2);
        sum1 += __shfl_xor_sync(0xFFFFFFFFu, sum1, 1);
        sum1 += __shfl_xor_sync(0xFFFFFFFFu, sum1, 2);
        if (tig == 0) {
            const int row0 = q16 * 16 + g;
            const int pidx = nt * 2 + nw;
            g_ps[(bh * LQ + row0) * 32 + pidx] = sum0;
            g_ps[(bh * LQ + row0 + 8) * 32 + pidx] = sum1;
        }
    }
}

// ---------------------------------------------------------------------------
// Kernel 4: P@V with hi-only fp16 V. CTA (qt 128q, ft 256f, h, b); 512 thr.
// ---------------------------------------------------------------------------
__global__ __launch_bounds__(512) void pv_kernel(float* __restrict__ out) {
    __shared__ float sm_iv[128];
    const int tid = threadIdx.x;
    const int w = tid >> 5, lane = tid & 31;
    const int g = lane >> 2, tig = lane & 3;
    const int qw = w & 3, fw = w >> 2;
    const int qt = blockIdx.x >> 1, ft = blockIdx.x & 1;
    const int h = blockIdx.y, b = blockIdx.z;
    const size_t bh = (size_t)(b * HH + h);

    if (tid < 128) {
        const float4* pp = (const float4*)(g_ps + (bh * LQ + (size_t)qt * 128 + tid) * 32);
        float s = 0.f;
#pragma unroll
        for (int i = 0; i < 8; i++) {
            float4 v = pp[i];
            s += v.x + v.y + v.z + v.w;
        }
        sm_iv[tid] = 1.0f / s;
    }
    __syncthreads();

    float iv[2][2];
#pragma unroll
    for (int mi = 0; mi < 2; mi++) {
        iv[mi][0] = sm_iv[qw * 32 + mi * 16 + g];
        iv[mi][1] = sm_iv[qw * 32 + mi * 16 + g + 8];
    }

    const float4* Abase[2];
#pragma unroll
    for (int mi = 0; mi < 2; mi++)
        Abase[mi] = (const float4*)(g_S +
            (((size_t)bh * 64 + qt * 8 + qw * 2 + mi) * 64) * 256) + lane;

    float acc[2][8][4] = {};

#pragma unroll 2
    for (int kc = 0; kc < 64; kc++) {
        uint32_t au[2][4];
#pragma unroll
        for (int mi = 0; mi < 2; mi++) {
            float4 f0 = Abase[mi][kc * 64];
            float4 f1 = Abase[mi][kc * 64 + 32];
            __half2 t;
            t = __floats2half2_rn(f0.x * iv[mi][0], f0.y * iv[mi][0]); au[mi][0] = *(uint32_t*)&t;
            t = __floats2half2_rn(f1.x * iv[mi][1], f1.y * iv[mi][1]); au[mi][1] = *(uint32_t*)&t;
            t = __floats2half2_rn(f0.z * iv[mi][0], f0.w * iv[mi][0]); au[mi][2] = *(uint32_t*)&t;
            t = __floats2half2_rn(f1.z * iv[mi][1], f1.w * iv[mi][1]); au[mi][3] = *(uint32_t*)&t;
        }
#pragma unroll
        for (int ni = 0; ni < 8; ni++) {
            const int f8 = ft * 32 + fw * 8 + ni;
            uint2 v = ((const uint2*)g_vt)[(((size_t)b * 64 + f8) * 64 + kc) * 32 + lane];
#pragma unroll
            for (int mi = 0; mi < 2; mi++)
                mma_f16(acc[mi][ni], au[mi][0], au[mi][1], au[mi][2], au[mi][3], v.x, v.y);
        }
    }

#pragma unroll
    for (int mi = 0; mi < 2; mi++) {
        const int q0 = qt * 128 + qw * 32 + mi * 16 + g;
#pragma unroll
        for (int ni = 0; ni < 8; ni++) {
            const int f = ft * 256 + fw * 64 + ni * 8 + tig * 2;
            float* op0 = out + ((size_t)q0 * BB + b) * (HH * FF) + h * FF + f;
            float* op1 = out + ((size_t)(q0 + 8) * BB + b) * (HH * FF) + h * FF + f;
            *(float2*)op0 = make_float2(acc[mi][ni][0], acc[mi][ni][1]);
            *(float2*)op1 = make_float2(acc[mi][ni][2], acc[mi][ni][3]);
        }
    }
}

// ---------------------------------------------------------------------------
extern "C" void kernel_launch(void* const* d_in, const int* in_sizes, int n_in,
                              void* d_out, int out_size) {
    const float* query = (const float*)d_in[0];
    const float* key   = (const float*)d_in[1];
    const float* value = (const float*)d_in[2];
    const float* Wk    = (const float*)d_in[3];
    const float* bk    = (const float*)d_in[4];
    float* out = (float*)d_out;

    __nv_bfloat16 *q1, *q2, *q3, *k1, *k2, *k3;
    cudaGetSymbolAddress((void**)&q1, g_wq1);
    cudaGetSymbolAddress((void**)&q2, g_wq2);
    cudaGetSymbolAddress((void**)&q3, g_wq3);
    cudaGetSymbolAddress((void**)&k1, g_wk1);
    cudaGetSymbolAddress((void**)&k2, g_wk2);
    cudaGetSymbolAddress((void**)&k3, g_wk3);

    cudaFuncSetAttribute(projmma_kernel, cudaFuncAttributeMaxDynamicSharedMemorySize, PROJ_SMEM);
    dim3 pg(128, HH);
    projmma_kernel<<<pg, 256, PROJ_SMEM>>>(query, Wk, bk, q1, q2, q3, TEMPS);
    projmma_kernel<<<pg, 256, PROJ_SMEM>>>(key, Wk, bk, k1, k2, k3, 1.0f);

    dim3 vg(FF / 32, LQ / 32, BB);
    vsplit_kernel<<<vg, 256>>>(value);

    cudaFuncSetAttribute(scores_kernel, cudaFuncAttributeMaxDynamicSharedMemorySize, SCORES_SMEM);
    dim3 sg(8 * 16, HH, BB);
    scores_kernel<<<sg, 256, SCORES_SMEM>>>();

    dim3 ag((LQ / 128) * 2, HH, BB);
    pv_kernel<<<ag, 512>>>(out);
}

// round 13
// speedup vs baseline: 3.8889x; 1.2364x over previous
#include <cuda_runtime.h>
#include <cuda_bf16.h>
#include <cuda_fp16.h>
#include <math.h>
#include <stdint.h>

#define LQ 1024
#define BB 16
#define FF 512
#define HH 8
#define KK 64
#define TEMPS 30.0f
#define BH 128

// ------------------------- static scratch -------------------------
// wq as A-fragments: [bh][q16 0..63][k16 0..3][lane] uint4 (a0..a3 bf16x2), 2 parts
__device__ __align__(16) uint4 g_wqA1[(size_t)BH * 64 * 4 * 32];
__device__ __align__(16) uint4 g_wqA2[(size_t)BH * 64 * 4 * 32];
// wk as B-fragments: [bh][n8 0..127][k16 0..3][lane] uint2 (b0,b1), 2 parts
__device__ __align__(16) uint2 g_wkB1[(size_t)BH * 128 * 4 * 32];
__device__ __align__(16) uint2 g_wkB2[(size_t)BH * 128 * 4 * 32];
// V (hi fp16) B-fragments: [b][f8 0..63][s16 0..63][lane] uint2
__device__ __align__(16) uint32_t g_vt[(size_t)BB * 64 * 64 * 32 * 2];
// P = exp(s - rowmax) fp16 A-fragments: [bh][q16][s16][lane] uint4
__device__ __align__(16) uint4 g_S16[(size_t)BH * 64 * 64 * 32];
// per-row 1 / sum(exp(s - rowmax))
__device__ __align__(16) float g_iv[(size_t)BH * LQ];

// ------------------------- helpers -------------------------
__device__ __forceinline__ void split2pack(float x, float y, uint32_t& hi, uint32_t& lo) {
    __nv_bfloat16 hx = __float2bfloat16(x), hy = __float2bfloat16(y);
    __nv_bfloat16 lx = __float2bfloat16(x - __bfloat162float(hx));
    __nv_bfloat16 ly = __float2bfloat16(y - __bfloat162float(hy));
    __nv_bfloat162 H = __halves2bfloat162(hx, hy);
    __nv_bfloat162 L = __halves2bfloat162(lx, ly);
    hi = *(uint32_t*)&H;
    lo = *(uint32_t*)&L;
}
__device__ __forceinline__ void mma_bf16(float c[4], uint32_t a0, uint32_t a1, uint32_t a2,
                                         uint32_t a3, uint32_t b0, uint32_t b1) {
    asm("mma.sync.aligned.m16n8k16.row.col.f32.bf16.bf16.f32 "
        "{%0,%1,%2,%3}, {%4,%5,%6,%7}, {%8,%9}, {%0,%1,%2,%3};"
        : "+f"(c[0]), "+f"(c[1]), "+f"(c[2]), "+f"(c[3])
        : "r"(a0), "r"(a1), "r"(a2), "r"(a3), "r"(b0), "r"(b1));
}
__device__ __forceinline__ void mma_f16(float c[4], uint32_t a0, uint32_t a1, uint32_t a2,
                                        uint32_t a3, uint32_t b0, uint32_t b1) {
    asm("mma.sync.aligned.m16n8k16.row.col.f32.f16.f16.f32 "
        "{%0,%1,%2,%3}, {%4,%5,%6,%7}, {%8,%9}, {%0,%1,%2,%3};"
        : "+f"(c[0]), "+f"(c[1]), "+f"(c[2]), "+f"(c[3])
        : "r"(a0), "r"(a1), "r"(a2), "r"(a3), "r"(b0), "r"(b1));
}
__device__ __forceinline__ void ldsm4(uint32_t& r0, uint32_t& r1, uint32_t& r2, uint32_t& r3,
                                      uint32_t a) {
    asm volatile("ldmatrix.sync.aligned.m8n8.x4.shared.b16 {%0,%1,%2,%3}, [%4];"
                 : "=r"(r0), "=r"(r1), "=r"(r2), "=r"(r3) : "r"(a));
}
__device__ __forceinline__ uint32_t smem_u32(const void* p) {
    uint32_t a;
    asm("{ .reg .u64 t; cvta.to.shared.u64 t, %1; cvt.u32.u64 %0, t; }" : "=r"(a) : "l"(p));
    return a;
}
#define SWZ(o) ((o) ^ (((o) >> 3) & 0x70))

extern __shared__ __align__(1024) char smx[];

__device__ __forceinline__ void split_store8_2(const float* v, char* d1, char* d2) {
    uint4 u1, u2;
    split2pack(v[0], v[1], u1.x, u2.x);
    split2pack(v[2], v[3], u1.y, u2.y);
    split2pack(v[4], v[5], u1.z, u2.z);
    split2pack(v[6], v[7], u1.w, u2.w);
    *(uint4*)d1 = u1;
    *(uint4*)d2 = u2;
}

// ---------------------------------------------------------------------------
// Kernel 1: projection via 2-part split-bf16 mma. CTA = 128q (one b,h) x 64n.
// K=512 in 8 staged chunks. Epilogue: +bias, L2-normalize, write fragment
// layouts: isQ -> A-fragments (scaled by TEMP); else -> B-fragments.
// ---------------------------------------------------------------------------
#define PA(p) ((p) * 16384)
#define PB(p) (32768 + (p) * 8192)
#define PROJ_SMEM 49152

__global__ __launch_bounds__(256) void projmma_kernel(const float* __restrict__ X,
                                                      const float* __restrict__ W,
                                                      const float* __restrict__ bias,
                                                      int isQ, float scale) {
    __shared__ float ssq[128][2];
    const uint32_t sb = smem_u32(smx);
    const int tid = threadIdx.x;
    const int w = tid >> 5, lane = tid & 31;
    const int g = lane >> 2, tig = lane & 3;
    const int qw = w >> 1, nw = w & 1;
    const int bx = blockIdx.x;
    const int qt = bx >> 4, b = bx & 15;
    const int h = blockIdx.y;
    const int n0 = h * 64;
    const size_t bh = (size_t)b * HH + h;

    const int mat = lane >> 3, rin = lane & 7;
    const int arow = (mat & 1) * 8 + rin, akh = mat >> 1;
    const int brow = (mat >> 1) * 8 + rin, bkh = mat & 1;

    float acc[2][4][4] = {};

    for (int kc64 = 0; kc64 < 8; kc64++) {
        // stage A: 128 rows (q = qt*128 + r of batch b) x 64 f32 -> 2 bf16 tiles
        {
            const int r = tid >> 1, half = tid & 1;
            const float4* src = (const float4*)(X +
                ((size_t)(qt * 128 + r) * BB + b) * FF + kc64 * 64 + half * 32);
#pragma unroll
            for (int j = 0; j < 4; j++) {
                float4 fa = src[2 * j], fb = src[2 * j + 1];
                float v[8] = {fa.x, fa.y, fa.z, fa.w, fb.x, fb.y, fb.z, fb.w};
                uint32_t d = SWZ((uint32_t)(r * 128 + half * 64 + j * 16));
                split_store8_2(v, smx + PA(0) + d, smx + PA(1) + d);
            }
        }
        // stage B (weights): 64 x 64 f32 -> 2 bf16 tiles
        {
            const int r = tid >> 2, q4 = tid & 3;
            const float4* src = (const float4*)(W + (size_t)(n0 + r) * FF + kc64 * 64 + q4 * 16);
#pragma unroll
            for (int j = 0; j < 2; j++) {
                float4 fa = src[2 * j], fb = src[2 * j + 1];
                float v[8] = {fa.x, fa.y, fa.z, fa.w, fb.x, fb.y, fb.z, fb.w};
                uint32_t d = SWZ((uint32_t)(r * 128 + q4 * 32 + j * 16));
                split_store8_2(v, smx + PB(0) + d, smx + PB(1) + d);
            }
        }
        __syncthreads();

#pragma unroll
        for (int kc = 0; kc < 4; kc++) {
            uint32_t A[2][2][4], Bf[2][2][4];
#pragma unroll
            for (int p = 0; p < 2; p++) {
#pragma unroll
                for (int mi = 0; mi < 2; mi++) {
                    uint32_t a = sb + PA(p) +
                        SWZ((uint32_t)((qw * 32 + mi * 16 + arow) * 128 + kc * 32 + akh * 16));
                    ldsm4(A[p][mi][0], A[p][mi][1], A[p][mi][2], A[p][mi][3], a);
                }
#pragma unroll
                for (int j = 0; j < 2; j++) {
                    uint32_t a = sb + PB(p) +
                        SWZ((uint32_t)((nw * 32 + j * 16 + brow) * 128 + kc * 32 + bkh * 16));
                    ldsm4(Bf[p][j][0], Bf[p][j][1], Bf[p][j][2], Bf[p][j][3], a);
                }
            }
            const int pa[3] = {0, 0, 1};
            const int pb[3] = {0, 1, 0};
#pragma unroll
            for (int p = 0; p < 3; p++)
#pragma unroll
                for (int mi = 0; mi < 2; mi++)
#pragma unroll
                    for (int j = 0; j < 2; j++) {
                        mma_bf16(acc[mi][2 * j], A[pa[p]][mi][0], A[pa[p]][mi][1],
                                 A[pa[p]][mi][2], A[pa[p]][mi][3], Bf[pb[p]][j][0], Bf[pb[p]][j][1]);
                        mma_bf16(acc[mi][2 * j + 1], A[pa[p]][mi][0], A[pa[p]][mi][1],
                                 A[pa[p]][mi][2], A[pa[p]][mi][3], Bf[pb[p]][j][2], Bf[pb[p]][j][3]);
                    }
        }
        __syncthreads();
    }

    // bias
#pragma unroll
    for (int ni = 0; ni < 4; ni++) {
        float2 bb = *(const float2*)(bias + n0 + nw * 32 + ni * 8 + tig * 2);
#pragma unroll
        for (int mi = 0; mi < 2; mi++) {
            acc[mi][ni][0] += bb.x; acc[mi][ni][1] += bb.y;
            acc[mi][ni][2] += bb.x; acc[mi][ni][3] += bb.y;
        }
    }

    // ssq partials, reduce over tig, cross-nw via smem
#pragma unroll
    for (int mi = 0; mi < 2; mi++) {
        float s0 = 0.f, s1 = 0.f;
#pragma unroll
        for (int ni = 0; ni < 4; ni++) {
            s0 = fmaf(acc[mi][ni][0], acc[mi][ni][0], s0);
            s0 = fmaf(acc[mi][ni][1], acc[mi][ni][1], s0);
            s1 = fmaf(acc[mi][ni][2], acc[mi][ni][2], s1);
            s1 = fmaf(acc[mi][ni][3], acc[mi][ni][3], s1);
        }
        s0 += __shfl_xor_sync(0xFFFFFFFFu, s0, 1);
        s0 += __shfl_xor_sync(0xFFFFFFFFu, s0, 2);
        s1 += __shfl_xor_sync(0xFFFFFFFFu, s1, 1);
        s1 += __shfl_xor_sync(0xFFFFFFFFu, s1, 2);
        if (tig == 0) {
            ssq[qw * 32 + mi * 16 + g][nw] = s0;
            ssq[qw * 32 + mi * 16 + g + 8][nw] = s1;
        }
    }
    __syncthreads();

    // epilogue: normalize + write fragment-layout outputs
#pragma unroll
    for (int mi = 0; mi < 2; mi++) {
        const int rg = qw * 32 + mi * 16 + g;
        const float sc0 = scale / fmaxf(sqrtf(ssq[rg][0] + ssq[rg][1]), 1e-12f);
        const float sc1 = scale / fmaxf(sqrtf(ssq[rg + 8][0] + ssq[rg + 8][1]), 1e-12f);
        const int q16 = qt * 8 + qw * 2 + mi;
#pragma unroll
        for (int jj = 0; jj < 2; jj++) {
            const int k16 = nw * 2 + jj;
            // scaled values: rows g (sc0) / g+8 (sc1), cols ni=2jj, 2jj+1
            float w0 = acc[mi][2 * jj][0] * sc0, w1 = acc[mi][2 * jj][1] * sc0;
            float w2 = acc[mi][2 * jj][2] * sc1, w3 = acc[mi][2 * jj][3] * sc1;
            float w4 = acc[mi][2 * jj + 1][0] * sc0, w5 = acc[mi][2 * jj + 1][1] * sc0;
            float w6 = acc[mi][2 * jj + 1][2] * sc1, w7 = acc[mi][2 * jj + 1][3] * sc1;
            if (isQ) {
                // A-fragment: a0=(g, k lo), a1=(g+8, k lo), a2=(g, k hi), a3=(g+8, k hi)
                uint4 u1, u2;
                split2pack(w0, w1, u1.x, u2.x);
                split2pack(w2, w3, u1.y, u2.y);
                split2pack(w4, w5, u1.z, u2.z);
                split2pack(w6, w7, u1.w, u2.w);
                const size_t idx = ((bh * 64 + q16) * 4 + k16) * 32 + lane;
                g_wqA1[idx] = u1;
                g_wqA2[idx] = u2;
            } else {
                // B-fragments: n8 = q16*2 (rows g), q16*2+1 (rows g+8)
                uint2 ua1, ua2, ub1, ub2;
                split2pack(w0, w1, ua1.x, ua2.x);
                split2pack(w4, w5, ua1.y, ua2.y);
                split2pack(w2, w3, ub1.x, ub2.x);
                split2pack(w6, w7, ub1.y, ub2.y);
                const size_t ia = ((bh * 128 + q16 * 2) * 4 + k16) * 32 + lane;
                const size_t ib = ((bh * 128 + q16 * 2 + 1) * 4 + k16) * 32 + lane;
                g_wkB1[ia] = ua1; g_wkB2[ia] = ua2;
                g_wkB1[ib] = ub1; g_wkB2[ib] = ub2;
            }
        }
    }
}

// ---------------------------------------------------------------------------
// Kernel 2: V -> B-fragment layout, fp16 hi only, packed per lane.
// ---------------------------------------------------------------------------
__global__ __launch_bounds__(256) void vsplit_kernel(const float* __restrict__ value) {
    __shared__ float t[32][33];   // [s][f]
    const int tid = threadIdx.x;
    const int f0 = blockIdx.x * 32, s0 = blockIdx.y * 32, b = blockIdx.z;

    for (int u = tid; u < 1024; u += 256) {
        int s = u >> 5, f = u & 31;
        t[s][f] = value[(size_t)(s0 + s) * (BB * FF) + b * FF + f0 + f];
    }
    __syncthreads();

    const int blk = tid >> 5, lane = tid & 31;
    const int sbk = blk >> 2, fb = blk & 3;
    const int g = lane >> 2, tig = lane & 3;
    const int s_l = sbk * 16 + tig * 2;
    const int f_l = fb * 8 + g;
    __half2 bh0 = __floats2half2_rn(t[s_l][f_l], t[s_l + 1][f_l]);
    __half2 bh1 = __floats2half2_rn(t[s_l + 8][f_l], t[s_l + 9][f_l]);
    uint2 u;
    u.x = *(uint32_t*)&bh0; u.y = *(uint32_t*)&bh1;
    const int f8 = (f0 >> 3) + fb;
    const int s16 = (s0 >> 4) + sbk;
    ((uint2*)g_vt)[(((size_t)b * 64 + f8) * 64 + s16) * 32 + lane] = u;
}

// ---------------------------------------------------------------------------
// Kernel 3: scores. CTA = 32q x 1024s (FULL rows), 512 thr, 16 warps of
// 32q x 64s. Fragment-native global loads, no smem staging, no ldmatrix.
// Exact per-row max + sum. Stores P = exp(s - m) fp16 A-fragments + 1/sum.
// ---------------------------------------------------------------------------
__global__ __launch_bounds__(512) void scores_kernel() {
    __shared__ float smax[32][17];
    __shared__ float ssum[32][17];
    __shared__ float sfm[32];
    const int tid = threadIdx.x;
    const int w = tid >> 5, lane = tid & 31;
    const int g = lane >> 2, tig = lane & 3;
    const int qt = blockIdx.x;          // 0..31, rows qt*32..+31
    const int h = blockIdx.y, b = blockIdx.z;
    const size_t bh = (size_t)b * HH + h;

    float acc[2][8][4] = {};

#pragma unroll
    for (int kc = 0; kc < 4; kc++) {
        uint4 A1[2], A2[2];
#pragma unroll
        for (int mi = 0; mi < 2; mi++) {
            const size_t ia = ((bh * 64 + qt * 2 + mi) * 4 + kc) * 32 + lane;
            A1[mi] = g_wqA1[ia];
            A2[mi] = g_wqA2[ia];
        }
#pragma unroll
        for (int ni = 0; ni < 8; ni++) {
            const size_t ibx = ((bh * 128 + w * 8 + ni) * 4 + kc) * 32 + lane;
            uint2 B1 = g_wkB1[ibx];
            uint2 B2 = g_wkB2[ibx];
#pragma unroll
            for (int mi = 0; mi < 2; mi++) {
                mma_bf16(acc[mi][ni], A1[mi].x, A1[mi].y, A1[mi].z, A1[mi].w, B1.x, B1.y);
                mma_bf16(acc[mi][ni], A1[mi].x, A1[mi].y, A1[mi].z, A1[mi].w, B2.x, B2.y);
                mma_bf16(acc[mi][ni], A2[mi].x, A2[mi].y, A2[mi].z, A2[mi].w, B1.x, B1.y);
            }
        }
    }

    // per-row max over this warp's 64 cols
#pragma unroll
    for (int mi = 0; mi < 2; mi++) {
        float rm0 = -1e30f, rm1 = -1e30f;
#pragma unroll
        for (int ni = 0; ni < 8; ni++) {
            rm0 = fmaxf(rm0, fmaxf(acc[mi][ni][0], acc[mi][ni][1]));
            rm1 = fmaxf(rm1, fmaxf(acc[mi][ni][2], acc[mi][ni][3]));
        }
        rm0 = fmaxf(rm0, __shfl_xor_sync(0xFFFFFFFFu, rm0, 1));
        rm0 = fmaxf(rm0, __shfl_xor_sync(0xFFFFFFFFu, rm0, 2));
        rm1 = fmaxf(rm1, __shfl_xor_sync(0xFFFFFFFFu, rm1, 1));
        rm1 = fmaxf(rm1, __shfl_xor_sync(0xFFFFFFFFu, rm1, 2));
        if (tig == 0) {
            smax[mi * 16 + g][w] = rm0;
            smax[mi * 16 + g + 8][w] = rm1;
        }
    }
    __syncthreads();
    if (tid < 32) {
        float m = smax[tid][0];
#pragma unroll
        for (int ww = 1; ww < 16; ww++) m = fmaxf(m, smax[tid][ww]);
        sfm[tid] = m;
    }
    __syncthreads();

    // exp(s - m), store fp16 fragments, accumulate row sums
#pragma unroll
    for (int mi = 0; mi < 2; mi++) {
        const float m0 = sfm[mi * 16 + g];
        const float m1 = sfm[mi * 16 + g + 8];
        float e[8][4];
        float sum0 = 0.f, sum1 = 0.f;
#pragma unroll
        for (int ni = 0; ni < 8; ni++) {
            e[ni][0] = __expf(acc[mi][ni][0] - m0);
            e[ni][1] = __expf(acc[mi][ni][1] - m0);
            e[ni][2] = __expf(acc[mi][ni][2] - m1);
            e[ni][3] = __expf(acc[mi][ni][3] - m1);
            sum0 += e[ni][0] + e[ni][1];
            sum1 += e[ni][2] + e[ni][3];
        }
#pragma unroll
        for (int j = 0; j < 4; j++) {
            __half2 h0 = __floats2half2_rn(e[2 * j][0], e[2 * j][1]);
            __half2 h1 = __floats2half2_rn(e[2 * j][2], e[2 * j][3]);
            __half2 h2 = __floats2half2_rn(e[2 * j + 1][0], e[2 * j + 1][1]);
            __half2 h3 = __floats2half2_rn(e[2 * j + 1][2], e[2 * j + 1][3]);
            uint4 u;
            u.x = *(uint32_t*)&h0; u.y = *(uint32_t*)&h1;
            u.z = *(uint32_t*)&h2; u.w = *(uint32_t*)&h3;
            g_S16[((bh * 64 + qt * 2 + mi) * 64 + w * 4 + j) * 32 + lane] = u;
        }
        sum0 += __shfl_xor_sync(0xFFFFFFFFu, sum0, 1);
        sum0 += __shfl_xor_sync(0xFFFFFFFFu, sum0, 2);
        sum1 += __shfl_xor_sync(0xFFFFFFFFu, sum1, 1);
        sum1 += __shfl_xor_sync(0xFFFFFFFFu, sum1, 2);
        if (tig == 0) {
            ssum[mi * 16 + g][w] = sum0;
            ssum[mi * 16 + g + 8][w] = sum1;
        }
    }
    __syncthreads();
    if (tid < 32) {
        float s = 0.f;
#pragma unroll
        for (int ww = 0; ww < 16; ww++) s += ssum[tid][ww];
        g_iv[bh * LQ + qt * 32 + tid] = 1.0f / s;
    }
}

// ---------------------------------------------------------------------------
// Kernel 4: P@V. CTA (qt 128q, ft 256f, h, b); 512 thr; warp = 32q x 64f.
// A = ready fp16 P fragments; normalization deferred to epilogue via g_iv.
// ---------------------------------------------------------------------------
__global__ __launch_bounds__(512) void pv_kernel(float* __restrict__ out) {
    __shared__ float sm_iv[128];
    const int tid = threadIdx.x;
    const int w = tid >> 5, lane = tid & 31;
    const int g = lane >> 2, tig = lane & 3;
    const int qw = w & 3, fw = w >> 2;
    const int qt = blockIdx.x >> 1, ft = blockIdx.x & 1;
    const int h = blockIdx.y, b = blockIdx.z;
    const size_t bh = (size_t)b * HH + h;

    if (tid < 128) sm_iv[tid] = g_iv[bh * LQ + (size_t)qt * 128 + tid];
    __syncthreads();

    float iv[2][2];
#pragma unroll
    for (int mi = 0; mi < 2; mi++) {
        iv[mi][0] = sm_iv[qw * 32 + mi * 16 + g];
        iv[mi][1] = sm_iv[qw * 32 + mi * 16 + g + 8];
    }

    const uint4* Abase[2];
#pragma unroll
    for (int mi = 0; mi < 2; mi++)
        Abase[mi] = g_S16 + (((size_t)bh * 64 + qt * 8 + qw * 2 + mi) * 64) * 32 + lane;

    float acc[2][8][4] = {};

#pragma unroll 4
    for (int kc = 0; kc < 64; kc++) {
        uint4 au[2];
        au[0] = Abase[0][(size_t)kc * 32];
        au[1] = Abase[1][(size_t)kc * 32];
#pragma unroll
        for (int ni = 0; ni < 8; ni++) {
            const int f8 = ft * 32 + fw * 8 + ni;
            uint2 v = ((const uint2*)g_vt)[(((size_t)b * 64 + f8) * 64 + kc) * 32 + lane];
#pragma unroll
            for (int mi = 0; mi < 2; mi++)
                mma_f16(acc[mi][ni], au[mi].x, au[mi].y, au[mi].z, au[mi].w, v.x, v.y);
        }
    }

#pragma unroll
    for (int mi = 0; mi < 2; mi++) {
        const int q0 = qt * 128 + qw * 32 + mi * 16 + g;
#pragma unroll
        for (int ni = 0; ni < 8; ni++) {
            const int f = ft * 256 + fw * 64 + ni * 8 + tig * 2;
            float* op0 = out + ((size_t)q0 * BB + b) * (HH * FF) + h * FF + f;
            float* op1 = out + ((size_t)(q0 + 8) * BB + b) * (HH * FF) + h * FF + f;
            *(float2*)op0 = make_float2(acc[mi][ni][0] * iv[mi][0], acc[mi][ni][1] * iv[mi][0]);
            *(float2*)op1 = make_float2(acc[mi][ni][2] * iv[mi][1], acc[mi][ni][3] * iv[mi][1]);
        }
    }
}

// ---------------------------------------------------------------------------
extern "C" void kernel_launch(void* const* d_in, const int* in_sizes, int n_in,
                              void* d_out, int out_size) {
    const float* query = (const float*)d_in[0];
    const float* key   = (const float*)d_in[1];
    const float* value = (const float*)d_in[2];
    const float* Wk    = (const float*)d_in[3];
    const float* bk    = (const float*)d_in[4];
    float* out = (float*)d_out;

    cudaFuncSetAttribute(projmma_kernel, cudaFuncAttributeMaxDynamicSharedMemorySize, PROJ_SMEM);
    dim3 pg(8 * 16, HH);   // (qt, b) x h
    projmma_kernel<<<pg, 256, PROJ_SMEM>>>(query, Wk, bk, 1, TEMPS);
    projmma_kernel<<<pg, 256, PROJ_SMEM>>>(key, Wk, bk, 0, 1.0f);

    dim3 vg(FF / 32, LQ / 32, BB);
    vsplit_kernel<<<vg, 256>>>(value);

    dim3 sg(LQ / 32, HH, BB);   // (32, 8, 16)
    scores_kernel<<<sg, 512>>>();

    dim3 ag((LQ / 128) * 2, HH, BB);  // (16, 8, 16)
    pv_kernel<<<ag, 512>>>(out);
}

// round 14
// speedup vs baseline: 5.2331x; 1.3457x over previous
#include <cuda_runtime.h>
#include <cuda_bf16.h>
#include <cuda_fp16.h>
#include <math.h>
#include <stdint.h>

#define LQ 1024
#define BB 16
#define FF 512
#define HH 8
#define KK 64
#define TEMPS 30.0f
#define BH 128

// ------------------------- static scratch -------------------------
// wq as A-fragments: [bh][q16 0..63][k16 0..3][lane] uint4, 2 parts
__device__ __align__(16) uint4 g_wqA1[(size_t)BH * 64 * 4 * 32];
__device__ __align__(16) uint4 g_wqA2[(size_t)BH * 64 * 4 * 32];
// wk as B-fragments: [bh][n8 0..127][k16 0..3][lane] uint2, 2 parts
__device__ __align__(16) uint2 g_wkB1[(size_t)BH * 128 * 4 * 32];
__device__ __align__(16) uint2 g_wkB2[(size_t)BH * 128 * 4 * 32];
// V (hi fp16) B-fragments: [b][f8 0..63][s16 0..63][lane] uint2
__device__ __align__(16) uint32_t g_vt[(size_t)BB * 64 * 64 * 32 * 2];

// ------------------------- helpers -------------------------
__device__ __forceinline__ void split2pack(float x, float y, uint32_t& hi, uint32_t& lo) {
    __nv_bfloat16 hx = __float2bfloat16(x), hy = __float2bfloat16(y);
    __nv_bfloat16 lx = __float2bfloat16(x - __bfloat162float(hx));
    __nv_bfloat16 ly = __float2bfloat16(y - __bfloat162float(hy));
    __nv_bfloat162 H = __halves2bfloat162(hx, hy);
    __nv_bfloat162 L = __halves2bfloat162(lx, ly);
    hi = *(uint32_t*)&H;
    lo = *(uint32_t*)&L;
}
__device__ __forceinline__ void mma_bf16(float c[4], uint32_t a0, uint32_t a1, uint32_t a2,
                                         uint32_t a3, uint32_t b0, uint32_t b1) {
    asm("mma.sync.aligned.m16n8k16.row.col.f32.bf16.bf16.f32 "
        "{%0,%1,%2,%3}, {%4,%5,%6,%7}, {%8,%9}, {%0,%1,%2,%3};"
        : "+f"(c[0]), "+f"(c[1]), "+f"(c[2]), "+f"(c[3])
        : "r"(a0), "r"(a1), "r"(a2), "r"(a3), "r"(b0), "r"(b1));
}
__device__ __forceinline__ void mma_f16(float c[4], uint32_t a0, uint32_t a1, uint32_t a2,
                                        uint32_t a3, uint32_t b0, uint32_t b1) {
    asm("mma.sync.aligned.m16n8k16.row.col.f32.f16.f16.f32 "
        "{%0,%1,%2,%3}, {%4,%5,%6,%7}, {%8,%9}, {%0,%1,%2,%3};"
        : "+f"(c[0]), "+f"(c[1]), "+f"(c[2]), "+f"(c[3])
        : "r"(a0), "r"(a1), "r"(a2), "r"(a3), "r"(b0), "r"(b1));
}
__device__ __forceinline__ void ldsm4(uint32_t& r0, uint32_t& r1, uint32_t& r2, uint32_t& r3,
                                      uint32_t a) {
    asm volatile("ldmatrix.sync.aligned.m8n8.x4.shared.b16 {%0,%1,%2,%3}, [%4];"
                 : "=r"(r0), "=r"(r1), "=r"(r2), "=r"(r3) : "r"(a));
}
__device__ __forceinline__ uint32_t smem_u32(const void* p) {
    uint32_t a;
    asm("{ .reg .u64 t; cvta.to.shared.u64 t, %1; cvt.u32.u64 %0, t; }" : "=r"(a) : "l"(p));
    return a;
}
#define SWZ(o) ((o) ^ (((o) >> 3) & 0x70))

extern __shared__ __align__(1024) char smx[];

__device__ __forceinline__ void split_store8_2(const float* v, char* d1, char* d2) {
    uint4 u1, u2;
    split2pack(v[0], v[1], u1.x, u2.x);
    split2pack(v[2], v[3], u1.y, u2.y);
    split2pack(v[4], v[5], u1.z, u2.z);
    split2pack(v[6], v[7], u1.w, u2.w);
    *(uint4*)d1 = u1;
    *(uint4*)d2 = u2;
}

// ---------------------------------------------------------------------------
// Kernel 1: projection (unchanged from round 13 — proven).
// ---------------------------------------------------------------------------
#define PA(p) ((p) * 16384)
#define PB(p) (32768 + (p) * 8192)
#define PROJ_SMEM 49152

__global__ __launch_bounds__(256) void projmma_kernel(const float* __restrict__ X,
                                                      const float* __restrict__ W,
                                                      const float* __restrict__ bias,
                                                      int isQ, float scale) {
    __shared__ float ssq[128][2];
    const uint32_t sb = smem_u32(smx);
    const int tid = threadIdx.x;
    const int w = tid >> 5, lane = tid & 31;
    const int g = lane >> 2, tig = lane & 3;
    const int qw = w >> 1, nw = w & 1;
    const int bx = blockIdx.x;
    const int qt = bx >> 4, b = bx & 15;
    const int h = blockIdx.y;
    const int n0 = h * 64;
    const size_t bh = (size_t)b * HH + h;

    const int mat = lane >> 3, rin = lane & 7;
    const int arow = (mat & 1) * 8 + rin, akh = mat >> 1;
    const int brow = (mat >> 1) * 8 + rin, bkh = mat & 1;

    float acc[2][4][4] = {};

    for (int kc64 = 0; kc64 < 8; kc64++) {
        {
            const int r = tid >> 1, half = tid & 1;
            const float4* src = (const float4*)(X +
                ((size_t)(qt * 128 + r) * BB + b) * FF + kc64 * 64 + half * 32);
#pragma unroll
            for (int j = 0; j < 4; j++) {
                float4 fa = src[2 * j], fb = src[2 * j + 1];
                float v[8] = {fa.x, fa.y, fa.z, fa.w, fb.x, fb.y, fb.z, fb.w};
                uint32_t d = SWZ((uint32_t)(r * 128 + half * 64 + j * 16));
                split_store8_2(v, smx + PA(0) + d, smx + PA(1) + d);
            }
        }
        {
            const int r = tid >> 2, q4 = tid & 3;
            const float4* src = (const float4*)(W + (size_t)(n0 + r) * FF + kc64 * 64 + q4 * 16);
#pragma unroll
            for (int j = 0; j < 2; j++) {
                float4 fa = src[2 * j], fb = src[2 * j + 1];
                float v[8] = {fa.x, fa.y, fa.z, fa.w, fb.x, fb.y, fb.z, fb.w};
                uint32_t d = SWZ((uint32_t)(r * 128 + q4 * 32 + j * 16));
                split_store8_2(v, smx + PB(0) + d, smx + PB(1) + d);
            }
        }
        __syncthreads();

#pragma unroll
        for (int kc = 0; kc < 4; kc++) {
            uint32_t A[2][2][4], Bf[2][2][4];
#pragma unroll
            for (int p = 0; p < 2; p++) {
#pragma unroll
                for (int mi = 0; mi < 2; mi++) {
                    uint32_t a = sb + PA(p) +
                        SWZ((uint32_t)((qw * 32 + mi * 16 + arow) * 128 + kc * 32 + akh * 16));
                    ldsm4(A[p][mi][0], A[p][mi][1], A[p][mi][2], A[p][mi][3], a);
                }
#pragma unroll
                for (int j = 0; j < 2; j++) {
                    uint32_t a = sb + PB(p) +
                        SWZ((uint32_t)((nw * 32 + j * 16 + brow) * 128 + kc * 32 + bkh * 16));
                    ldsm4(Bf[p][j][0], Bf[p][j][1], Bf[p][j][2], Bf[p][j][3], a);
                }
            }
            const int pa[3] = {0, 0, 1};
            const int pb[3] = {0, 1, 0};
#pragma unroll
            for (int p = 0; p < 3; p++)
#pragma unroll
                for (int mi = 0; mi < 2; mi++)
#pragma unroll
                    for (int j = 0; j < 2; j++) {
                        mma_bf16(acc[mi][2 * j], A[pa[p]][mi][0], A[pa[p]][mi][1],
                                 A[pa[p]][mi][2], A[pa[p]][mi][3], Bf[pb[p]][j][0], Bf[pb[p]][j][1]);
                        mma_bf16(acc[mi][2 * j + 1], A[pa[p]][mi][0], A[pa[p]][mi][1],
                                 A[pa[p]][mi][2], A[pa[p]][mi][3], Bf[pb[p]][j][2], Bf[pb[p]][j][3]);
                    }
        }
        __syncthreads();
    }

#pragma unroll
    for (int ni = 0; ni < 4; ni++) {
        float2 bb = *(const float2*)(bias + n0 + nw * 32 + ni * 8 + tig * 2);
#pragma unroll
        for (int mi = 0; mi < 2; mi++) {
            acc[mi][ni][0] += bb.x; acc[mi][ni][1] += bb.y;
            acc[mi][ni][2] += bb.x; acc[mi][ni][3] += bb.y;
        }
    }

#pragma unroll
    for (int mi = 0; mi < 2; mi++) {
        float s0 = 0.f, s1 = 0.f;
#pragma unroll
        for (int ni = 0; ni < 4; ni++) {
            s0 = fmaf(acc[mi][ni][0], acc[mi][ni][0], s0);
            s0 = fmaf(acc[mi][ni][1], acc[mi][ni][1], s0);
            s1 = fmaf(acc[mi][ni][2], acc[mi][ni][2], s1);
            s1 = fmaf(acc[mi][ni][3], acc[mi][ni][3], s1);
        }
        s0 += __shfl_xor_sync(0xFFFFFFFFu, s0, 1);
        s0 += __shfl_xor_sync(0xFFFFFFFFu, s0, 2);
        s1 += __shfl_xor_sync(0xFFFFFFFFu, s1, 1);
        s1 += __shfl_xor_sync(0xFFFFFFFFu, s1, 2);
        if (tig == 0) {
            ssq[qw * 32 + mi * 16 + g][nw] = s0;
            ssq[qw * 32 + mi * 16 + g + 8][nw] = s1;
        }
    }
    __syncthreads();

#pragma unroll
    for (int mi = 0; mi < 2; mi++) {
        const int rg = qw * 32 + mi * 16 + g;
        const float sc0 = scale / fmaxf(sqrtf(ssq[rg][0] + ssq[rg][1]), 1e-12f);
        const float sc1 = scale / fmaxf(sqrtf(ssq[rg + 8][0] + ssq[rg + 8][1]), 1e-12f);
        const int q16 = qt * 8 + qw * 2 + mi;
#pragma unroll
        for (int jj = 0; jj < 2; jj++) {
            const int k16 = nw * 2 + jj;
            float w0 = acc[mi][2 * jj][0] * sc0, w1 = acc[mi][2 * jj][1] * sc0;
            float w2 = acc[mi][2 * jj][2] * sc1, w3 = acc[mi][2 * jj][3] * sc1;
            float w4 = acc[mi][2 * jj + 1][0] * sc0, w5 = acc[mi][2 * jj + 1][1] * sc0;
            float w6 = acc[mi][2 * jj + 1][2] * sc1, w7 = acc[mi][2 * jj + 1][3] * sc1;
            if (isQ) {
                uint4 u1, u2;
                split2pack(w0, w1, u1.x, u2.x);
                split2pack(w2, w3, u1.y, u2.y);
                split2pack(w4, w5, u1.z, u2.z);
                split2pack(w6, w7, u1.w, u2.w);
                const size_t idx = ((bh * 64 + q16) * 4 + k16) * 32 + lane;
                g_wqA1[idx] = u1;
                g_wqA2[idx] = u2;
            } else {
                uint2 ua1, ua2, ub1, ub2;
                split2pack(w0, w1, ua1.x, ua2.x);
                split2pack(w4, w5, ua1.y, ua2.y);
                split2pack(w2, w3, ub1.x, ub2.x);
                split2pack(w6, w7, ub1.y, ub2.y);
                const size_t ia = ((bh * 128 + q16 * 2) * 4 + k16) * 32 + lane;
                const size_t ib = ((bh * 128 + q16 * 2 + 1) * 4 + k16) * 32 + lane;
                g_wkB1[ia] = ua1; g_wkB2[ia] = ua2;
                g_wkB1[ib] = ub1; g_wkB2[ib] = ub2;
            }
        }
    }
}

// ---------------------------------------------------------------------------
// Kernel 2: V -> B-fragment layout (unchanged).
// ---------------------------------------------------------------------------
__global__ __launch_bounds__(256) void vsplit_kernel(const float* __restrict__ value) {
    __shared__ float t[32][33];
    const int tid = threadIdx.x;
    const int f0 = blockIdx.x * 32, s0 = blockIdx.y * 32, b = blockIdx.z;

    for (int u = tid; u < 1024; u += 256) {
        int s = u >> 5, f = u & 31;
        t[s][f] = value[(size_t)(s0 + s) * (BB * FF) + b * FF + f0 + f];
    }
    __syncthreads();

    const int blk = tid >> 5, lane = tid & 31;
    const int sbk = blk >> 2, fb = blk & 3;
    const int g = lane >> 2, tig = lane & 3;
    const int s_l = sbk * 16 + tig * 2;
    const int f_l = fb * 8 + g;
    __half2 bh0 = __floats2half2_rn(t[s_l][f_l], t[s_l + 1][f_l]);
    __half2 bh1 = __floats2half2_rn(t[s_l + 8][f_l], t[s_l + 9][f_l]);
    uint2 u;
    u.x = *(uint32_t*)&bh0; u.y = *(uint32_t*)&bh1;
    const int f8 = (f0 >> 3) + fb;
    const int s16 = (s0 >> 4) + sbk;
    ((uint2*)g_vt)[(((size_t)b * 64 + f8) * 64 + s16) * 32 + lane] = u;
}

// ---------------------------------------------------------------------------
// Kernel 3 (FUSED): flash attention. CTA = 64q x 512f, 512 thr, 16 warps.
// Loop 8 s-chunks of 128. Per chunk: S (3-pass split-bf16 mma, wq from smem,
// wk frags from global) -> online softmax (exact running max/sum, O rescale)
// -> P fp16 A-frags via smem -> PV mma (V frags from global).
// ---------------------------------------------------------------------------
#define FWQ   0        // 16384: wq frag blobs [q16l 4][kc 4][p 2] x 512B
#define FPB   16384    // 16384: P frag blobs [q16l 4][s16l 8] x 512B
#define FM    32768    // 256: running max
#define FL    33024    // 256: running sum
#define FSCL  33280    // 256: rescale / final inv
#define FMN   33536    // 256: new max
#define FSMAX 33792    // 64*9*4 = 2304
#define FPSUM 36096    // 2304
#define FUSED_SMEM 38400

__global__ __launch_bounds__(512) void attn_kernel(float* __restrict__ out) {
    const int tid = threadIdx.x;
    const int w = tid >> 5, lane = tid & 31;
    const int g = lane >> 2, tig = lane & 3;
    const int qw = w >> 3, xw = w & 7;   // qw: 32q group; xw: sw (S) / fw (PV)
    const int qt = blockIdx.x;           // 0..15 (64 q each)
    const int h = blockIdx.y, b = blockIdx.z;
    const size_t bh = (size_t)b * HH + h;

    float* sm_m   = (float*)(smx + FM);
    float* sm_l   = (float*)(smx + FL);
    float* sm_scl = (float*)(smx + FSCL);
    float* sm_mn  = (float*)(smx + FMN);
    float* sm_max = (float*)(smx + FSMAX);   // [64][9]
    float* sm_ps  = (float*)(smx + FPSUM);   // [64][9]

    // prologue: stage wq A-frags (4 q16 x 4 kc x 2 parts) into smem
    for (int u = tid; u < 1024; u += 512) {
        const int q16l = u >> 8, kc = (u >> 6) & 3, p = (u >> 5) & 1, ln = u & 31;
        const uint4* src = (p ? g_wqA2 : g_wqA1) +
            ((bh * 64 + qt * 4 + q16l) * 4 + kc) * 32 + ln;
        *(uint4*)(smx + FWQ + u * 16) = *src;
    }
    if (tid < 64) { sm_m[tid] = -1e30f; sm_l[tid] = 0.f; }
    for (int u = tid; u < 64 * 9; u += 512) sm_ps[u] = 0.f;
    __syncthreads();

    float oacc[2][8][4] = {};
    const int r0 = qw * 32 + g;   // + mi*16 (+8)

    for (int sc = 0; sc < 8; sc++) {
        // ---- S phase: warp computes S[32q x 16s] at s16 = sc*8 + xw ----
        float sacc[2][2][4] = {};
#pragma unroll
        for (int kc = 0; kc < 4; kc++) {
            uint4 a[2][2];
#pragma unroll
            for (int mi = 0; mi < 2; mi++)
#pragma unroll
                for (int p = 0; p < 2; p++)
                    a[mi][p] = *(const uint4*)(smx + FWQ +
                        (((qw * 2 + mi) * 4 + kc) * 2 + p) * 512 + lane * 16);
#pragma unroll
            for (int nj = 0; nj < 2; nj++) {
                const int n8 = (sc * 8 + xw) * 2 + nj;
                const size_t ib = ((bh * 128 + n8) * 4 + kc) * 32 + lane;
                uint2 B1 = g_wkB1[ib];
                uint2 B2 = g_wkB2[ib];
#pragma unroll
                for (int mi = 0; mi < 2; mi++) {
                    mma_bf16(sacc[mi][nj], a[mi][0].x, a[mi][0].y, a[mi][0].z, a[mi][0].w, B1.x, B1.y);
                    mma_bf16(sacc[mi][nj], a[mi][0].x, a[mi][0].y, a[mi][0].z, a[mi][0].w, B2.x, B2.y);
                    mma_bf16(sacc[mi][nj], a[mi][1].x, a[mi][1].y, a[mi][1].z, a[mi][1].w, B1.x, B1.y);
                }
            }
        }

        // ---- chunk max ----
#pragma unroll
        for (int mi = 0; mi < 2; mi++) {
            float rm0 = fmaxf(fmaxf(sacc[mi][0][0], sacc[mi][0][1]),
                              fmaxf(sacc[mi][1][0], sacc[mi][1][1]));
            float rm1 = fmaxf(fmaxf(sacc[mi][0][2], sacc[mi][0][3]),
                              fmaxf(sacc[mi][1][2], sacc[mi][1][3]));
            rm0 = fmaxf(rm0, __shfl_xor_sync(0xFFFFFFFFu, rm0, 1));
            rm0 = fmaxf(rm0, __shfl_xor_sync(0xFFFFFFFFu, rm0, 2));
            rm1 = fmaxf(rm1, __shfl_xor_sync(0xFFFFFFFFu, rm1, 1));
            rm1 = fmaxf(rm1, __shfl_xor_sync(0xFFFFFFFFu, rm1, 2));
            if (tig == 0) {
                sm_max[(r0 + mi * 16) * 9 + xw] = rm0;
                sm_max[(r0 + mi * 16 + 8) * 9 + xw] = rm1;
            }
        }
        __syncthreads();

        // ---- running max / sum update (one thread per row) ----
        if (tid < 64) {
            const float* px = sm_ps + tid * 9;
            float ps = px[0] + px[1] + px[2] + px[3] + px[4] + px[5] + px[6] + px[7];
            const float* mx = sm_max + tid * 9;
            float cm = fmaxf(fmaxf(fmaxf(mx[0], mx[1]), fmaxf(mx[2], mx[3])),
                             fmaxf(fmaxf(mx[4], mx[5]), fmaxf(mx[6], mx[7])));
            float Mo = sm_m[tid];
            float Mn = fmaxf(Mo, cm);
            float s = __expf(Mo - Mn);
            sm_m[tid] = Mn;
            sm_mn[tid] = Mn;
            sm_scl[tid] = s;
            sm_l[tid] = (sm_l[tid] + ps) * s;
        }
        __syncthreads();

        // ---- P = exp(s - Mn), write fp16 A-frags to smem, rescale oacc ----
#pragma unroll
        for (int mi = 0; mi < 2; mi++) {
            const float mn0 = sm_mn[r0 + mi * 16];
            const float mn1 = sm_mn[r0 + mi * 16 + 8];
            float e[2][4];
#pragma unroll
            for (int nj = 0; nj < 2; nj++) {
                e[nj][0] = __expf(sacc[mi][nj][0] - mn0);
                e[nj][1] = __expf(sacc[mi][nj][1] - mn0);
                e[nj][2] = __expf(sacc[mi][nj][2] - mn1);
                e[nj][3] = __expf(sacc[mi][nj][3] - mn1);
            }
            float p0 = e[0][0] + e[0][1] + e[1][0] + e[1][1];
            float p1 = e[0][2] + e[0][3] + e[1][2] + e[1][3];
            p0 += __shfl_xor_sync(0xFFFFFFFFu, p0, 1);
            p0 += __shfl_xor_sync(0xFFFFFFFFu, p0, 2);
            p1 += __shfl_xor_sync(0xFFFFFFFFu, p1, 1);
            p1 += __shfl_xor_sync(0xFFFFFFFFu, p1, 2);
            if (tig == 0) {
                sm_ps[(r0 + mi * 16) * 9 + xw] = p0;
                sm_ps[(r0 + mi * 16 + 8) * 9 + xw] = p1;
            }
            __half2 h0 = __floats2half2_rn(e[0][0], e[0][1]);
            __half2 h1 = __floats2half2_rn(e[0][2], e[0][3]);
            __half2 h2 = __floats2half2_rn(e[1][0], e[1][1]);
            __half2 h3 = __floats2half2_rn(e[1][2], e[1][3]);
            uint4 u;
            u.x = *(uint32_t*)&h0; u.y = *(uint32_t*)&h1;
            u.z = *(uint32_t*)&h2; u.w = *(uint32_t*)&h3;
            *(uint4*)(smx + FPB + ((qw * 2 + mi) * 8 + xw) * 512 + lane * 16) = u;

            const float s0 = sm_scl[r0 + mi * 16];
            const float s1 = sm_scl[r0 + mi * 16 + 8];
#pragma unroll
            for (int ni = 0; ni < 8; ni++) {
                oacc[mi][ni][0] *= s0; oacc[mi][ni][1] *= s0;
                oacc[mi][ni][2] *= s1; oacc[mi][ni][3] *= s1;
            }
        }
        __syncthreads();

        // ---- PV phase: warp = 32q x 64f (f8 = xw*8 + ni) ----
#pragma unroll
        for (int kk = 0; kk < 8; kk++) {
            uint4 au0 = *(const uint4*)(smx + FPB + ((qw * 2 + 0) * 8 + kk) * 512 + lane * 16);
            uint4 au1 = *(const uint4*)(smx + FPB + ((qw * 2 + 1) * 8 + kk) * 512 + lane * 16);
#pragma unroll
            for (int ni = 0; ni < 8; ni++) {
                uint2 v = ((const uint2*)g_vt)[
                    (((size_t)b * 64 + xw * 8 + ni) * 64 + sc * 8 + kk) * 32 + lane];
                mma_f16(oacc[0][ni], au0.x, au0.y, au0.z, au0.w, v.x, v.y);
                mma_f16(oacc[1][ni], au1.x, au1.y, au1.z, au1.w, v.x, v.y);
            }
        }
        __syncthreads();
    }

    // ---- epilogue: final row sums -> inverse, scale, store ----
    if (tid < 64) {
        const float* px = sm_ps + tid * 9;
        float ps = px[0] + px[1] + px[2] + px[3] + px[4] + px[5] + px[6] + px[7];
        sm_scl[tid] = 1.0f / (sm_l[tid] + ps);
    }
    __syncthreads();

#pragma unroll
    for (int mi = 0; mi < 2; mi++) {
        const float iv0 = sm_scl[r0 + mi * 16];
        const float iv1 = sm_scl[r0 + mi * 16 + 8];
        const int q0 = qt * 64 + qw * 32 + mi * 16 + g;
#pragma unroll
        for (int ni = 0; ni < 8; ni++) {
            const int f = (xw * 8 + ni) * 8 + tig * 2;
            float* op0 = out + ((size_t)q0 * BB + b) * (HH * FF) + h * FF + f;
            float* op1 = out + ((size_t)(q0 + 8) * BB + b) * (HH * FF) + h * FF + f;
            *(float2*)op0 = make_float2(oacc[mi][ni][0] * iv0, oacc[mi][ni][1] * iv0);
            *(float2*)op1 = make_float2(oacc[mi][ni][2] * iv1, oacc[mi][ni][3] * iv1);
        }
    }
}

// ---------------------------------------------------------------------------
extern "C" void kernel_launch(void* const* d_in, const int* in_sizes, int n_in,
                              void* d_out, int out_size) {
    const float* query = (const float*)d_in[0];
    const float* key   = (const float*)d_in[1];
    const float* value = (const float*)d_in[2];
    const float* Wk    = (const float*)d_in[3];
    const float* bk    = (const float*)d_in[4];
    float* out = (float*)d_out;

    cudaFuncSetAttribute(projmma_kernel, cudaFuncAttributeMaxDynamicSharedMemorySize, PROJ_SMEM);
    dim3 pg(8 * 16, HH);
    projmma_kernel<<<pg, 256, PROJ_SMEM>>>(query, Wk, bk, 1, TEMPS);
    projmma_kernel<<<pg, 256, PROJ_SMEM>>>(key, Wk, bk, 0, 1.0f);

    dim3 vg(FF / 32, LQ / 32, BB);
    vsplit_kernel<<<vg, 256>>>(value);

    dim3 ag(16, HH, BB);   // (qt, h, b) = 2048 CTAs
    attn_kernel<<<ag, 512, FUSED_SMEM>>>(out);
}

// round 15
// speedup vs baseline: 5.8359x; 1.1152x over previous
#include <cuda_runtime.h>
#include <cuda_bf16.h>
#include <cuda_fp16.h>
#include <math.h>
#include <stdint.h>

#define LQ 1024
#define BB 16
#define FF 512
#define HH 8
#define KK 64
#define TEMPS 30.0f
#define BH 128

// ------------------------- static scratch -------------------------
// wq as A-fragments: [bh][q16 0..63][k16 0..3][lane] uint4, 2 parts
__device__ __align__(16) uint4 g_wqA1[(size_t)BH * 64 * 4 * 32];
__device__ __align__(16) uint4 g_wqA2[(size_t)BH * 64 * 4 * 32];
// wk as B-fragments: [bh][n8 0..127][k16 0..3][lane] uint2, 2 parts
__device__ __align__(16) uint2 g_wkB1[(size_t)BH * 128 * 4 * 32];
__device__ __align__(16) uint2 g_wkB2[(size_t)BH * 128 * 4 * 32];
// V (hi fp16) B-fragments: [b][f8 0..63][s16 0..63][lane] uint2
__device__ __align__(16) uint32_t g_vt[(size_t)BB * 64 * 64 * 32 * 2];

// ------------------------- helpers -------------------------
__device__ __forceinline__ void split2pack(float x, float y, uint32_t& hi, uint32_t& lo) {
    __nv_bfloat16 hx = __float2bfloat16(x), hy = __float2bfloat16(y);
    __nv_bfloat16 lx = __float2bfloat16(x - __bfloat162float(hx));
    __nv_bfloat16 ly = __float2bfloat16(y - __bfloat162float(hy));
    __nv_bfloat162 H = __halves2bfloat162(hx, hy);
    __nv_bfloat162 L = __halves2bfloat162(lx, ly);
    hi = *(uint32_t*)&H;
    lo = *(uint32_t*)&L;
}
__device__ __forceinline__ void mma_bf16(float c[4], uint32_t a0, uint32_t a1, uint32_t a2,
                                         uint32_t a3, uint32_t b0, uint32_t b1) {
    asm("mma.sync.aligned.m16n8k16.row.col.f32.bf16.bf16.f32 "
        "{%0,%1,%2,%3}, {%4,%5,%6,%7}, {%8,%9}, {%0,%1,%2,%3};"
        : "+f"(c[0]), "+f"(c[1]), "+f"(c[2]), "+f"(c[3])
        : "r"(a0), "r"(a1), "r"(a2), "r"(a3), "r"(b0), "r"(b1));
}
__device__ __forceinline__ void mma_f16(float c[4], uint32_t a0, uint32_t a1, uint32_t a2,
                                        uint32_t a3, uint32_t b0, uint32_t b1) {
    asm("mma.sync.aligned.m16n8k16.row.col.f32.f16.f16.f32 "
        "{%0,%1,%2,%3}, {%4,%5,%6,%7}, {%8,%9}, {%0,%1,%2,%3};"
        : "+f"(c[0]), "+f"(c[1]), "+f"(c[2]), "+f"(c[3])
        : "r"(a0), "r"(a1), "r"(a2), "r"(a3), "r"(b0), "r"(b1));
}
__device__ __forceinline__ void ldsm4(uint32_t& r0, uint32_t& r1, uint32_t& r2, uint32_t& r3,
                                      uint32_t a) {
    asm volatile("ldmatrix.sync.aligned.m8n8.x4.shared.b16 {%0,%1,%2,%3}, [%4];"
                 : "=r"(r0), "=r"(r1), "=r"(r2), "=r"(r3) : "r"(a));
}
__device__ __forceinline__ uint32_t smem_u32(const void* p) {
    uint32_t a;
    asm("{ .reg .u64 t; cvta.to.shared.u64 t, %1; cvt.u32.u64 %0, t; }" : "=r"(a) : "l"(p));
    return a;
}
#define SWZ(o) ((o) ^ (((o) >> 3) & 0x70))

extern __shared__ __align__(1024) char smx[];

__device__ __forceinline__ void split_store8_2(const float* v, char* d1, char* d2) {
    uint4 u1, u2;
    split2pack(v[0], v[1], u1.x, u2.x);
    split2pack(v[2], v[3], u1.y, u2.y);
    split2pack(v[4], v[5], u1.z, u2.z);
    split2pack(v[6], v[7], u1.w, u2.w);
    *(uint4*)d1 = u1;
    *(uint4*)d2 = u2;
}

// ---------------------------------------------------------------------------
// Kernel 1: projection (round-13 proven; q and k fused via blockIdx.z).
// ---------------------------------------------------------------------------
#define PA(p) ((p) * 16384)
#define PB(p) (32768 + (p) * 8192)
#define PROJ_SMEM 49152

__global__ __launch_bounds__(256) void projmma_kernel(const float* __restrict__ Q,
                                                      const float* __restrict__ Kx,
                                                      const float* __restrict__ W,
                                                      const float* __restrict__ bias) {
    __shared__ float ssq[128][2];
    const uint32_t sb = smem_u32(smx);
    const int tid = threadIdx.x;
    const int w = tid >> 5, lane = tid & 31;
    const int g = lane >> 2, tig = lane & 3;
    const int qw = w >> 1, nw = w & 1;
    const int bx = blockIdx.x;
    const int qt = bx >> 4, b = bx & 15;
    const int h = blockIdx.y;
    const int isQ = (blockIdx.z == 0);
    const float scale = isQ ? TEMPS : 1.0f;
    const float* X = isQ ? Q : Kx;
    const int n0 = h * 64;
    const size_t bh = (size_t)b * HH + h;

    const int mat = lane >> 3, rin = lane & 7;
    const int arow = (mat & 1) * 8 + rin, akh = mat >> 1;
    const int brow = (mat >> 1) * 8 + rin, bkh = mat & 1;

    float acc[2][4][4] = {};

    for (int kc64 = 0; kc64 < 8; kc64++) {
        {
            const int r = tid >> 1, half = tid & 1;
            const float4* src = (const float4*)(X +
                ((size_t)(qt * 128 + r) * BB + b) * FF + kc64 * 64 + half * 32);
#pragma unroll
            for (int j = 0; j < 4; j++) {
                float4 fa = src[2 * j], fb = src[2 * j + 1];
                float v[8] = {fa.x, fa.y, fa.z, fa.w, fb.x, fb.y, fb.z, fb.w};
                uint32_t d = SWZ((uint32_t)(r * 128 + half * 64 + j * 16));
                split_store8_2(v, smx + PA(0) + d, smx + PA(1) + d);
            }
        }
        {
            const int r = tid >> 2, q4 = tid & 3;
            const float4* src = (const float4*)(W + (size_t)(n0 + r) * FF + kc64 * 64 + q4 * 16);
#pragma unroll
            for (int j = 0; j < 2; j++) {
                float4 fa = src[2 * j], fb = src[2 * j + 1];
                float v[8] = {fa.x, fa.y, fa.z, fa.w, fb.x, fb.y, fb.z, fb.w};
                uint32_t d = SWZ((uint32_t)(r * 128 + q4 * 32 + j * 16));
                split_store8_2(v, smx + PB(0) + d, smx + PB(1) + d);
            }
        }
        __syncthreads();

#pragma unroll
        for (int kc = 0; kc < 4; kc++) {
            uint32_t A[2][2][4], Bf[2][2][4];
#pragma unroll
            for (int p = 0; p < 2; p++) {
#pragma unroll
                for (int mi = 0; mi < 2; mi++) {
                    uint32_t a = sb + PA(p) +
                        SWZ((uint32_t)((qw * 32 + mi * 16 + arow) * 128 + kc * 32 + akh * 16));
                    ldsm4(A[p][mi][0], A[p][mi][1], A[p][mi][2], A[p][mi][3], a);
                }
#pragma unroll
                for (int j = 0; j < 2; j++) {
                    uint32_t a = sb + PB(p) +
                        SWZ((uint32_t)((nw * 32 + j * 16 + brow) * 128 + kc * 32 + bkh * 16));
                    ldsm4(Bf[p][j][0], Bf[p][j][1], Bf[p][j][2], Bf[p][j][3], a);
                }
            }
            const int pa[3] = {0, 0, 1};
            const int pb[3] = {0, 1, 0};
#pragma unroll
            for (int p = 0; p < 3; p++)
#pragma unroll
                for (int mi = 0; mi < 2; mi++)
#pragma unroll
                    for (int j = 0; j < 2; j++) {
                        mma_bf16(acc[mi][2 * j], A[pa[p]][mi][0], A[pa[p]][mi][1],
                                 A[pa[p]][mi][2], A[pa[p]][mi][3], Bf[pb[p]][j][0], Bf[pb[p]][j][1]);
                        mma_bf16(acc[mi][2 * j + 1], A[pa[p]][mi][0], A[pa[p]][mi][1],
                                 A[pa[p]][mi][2], A[pa[p]][mi][3], Bf[pb[p]][j][2], Bf[pb[p]][j][3]);
                    }
        }
        __syncthreads();
    }

#pragma unroll
    for (int ni = 0; ni < 4; ni++) {
        float2 bb = *(const float2*)(bias + n0 + nw * 32 + ni * 8 + tig * 2);
#pragma unroll
        for (int mi = 0; mi < 2; mi++) {
            acc[mi][ni][0] += bb.x; acc[mi][ni][1] += bb.y;
            acc[mi][ni][2] += bb.x; acc[mi][ni][3] += bb.y;
        }
    }

#pragma unroll
    for (int mi = 0; mi < 2; mi++) {
        float s0 = 0.f, s1 = 0.f;
#pragma unroll
        for (int ni = 0; ni < 4; ni++) {
            s0 = fmaf(acc[mi][ni][0], acc[mi][ni][0], s0);
            s0 = fmaf(acc[mi][ni][1], acc[mi][ni][1], s0);
            s1 = fmaf(acc[mi][ni][2], acc[mi][ni][2], s1);
            s1 = fmaf(acc[mi][ni][3], acc[mi][ni][3], s1);
        }
        s0 += __shfl_xor_sync(0xFFFFFFFFu, s0, 1);
        s0 += __shfl_xor_sync(0xFFFFFFFFu, s0, 2);
        s1 += __shfl_xor_sync(0xFFFFFFFFu, s1, 1);
        s1 += __shfl_xor_sync(0xFFFFFFFFu, s1, 2);
        if (tig == 0) {
            ssq[qw * 32 + mi * 16 + g][nw] = s0;
            ssq[qw * 32 + mi * 16 + g + 8][nw] = s1;
        }
    }
    __syncthreads();

#pragma unroll
    for (int mi = 0; mi < 2; mi++) {
        const int rg = qw * 32 + mi * 16 + g;
        const float sc0 = scale / fmaxf(sqrtf(ssq[rg][0] + ssq[rg][1]), 1e-12f);
        const float sc1 = scale / fmaxf(sqrtf(ssq[rg + 8][0] + ssq[rg + 8][1]), 1e-12f);
        const int q16 = qt * 8 + qw * 2 + mi;
#pragma unroll
        for (int jj = 0; jj < 2; jj++) {
            const int k16 = nw * 2 + jj;
            float w0 = acc[mi][2 * jj][0] * sc0, w1 = acc[mi][2 * jj][1] * sc0;
            float w2 = acc[mi][2 * jj][2] * sc1, w3 = acc[mi][2 * jj][3] * sc1;
            float w4 = acc[mi][2 * jj + 1][0] * sc0, w5 = acc[mi][2 * jj + 1][1] * sc0;
            float w6 = acc[mi][2 * jj + 1][2] * sc1, w7 = acc[mi][2 * jj + 1][3] * sc1;
            if (isQ) {
                uint4 u1, u2;
                split2pack(w0, w1, u1.x, u2.x);
                split2pack(w2, w3, u1.y, u2.y);
                split2pack(w4, w5, u1.z, u2.z);
                split2pack(w6, w7, u1.w, u2.w);
                const size_t idx = ((bh * 64 + q16) * 4 + k16) * 32 + lane;
                g_wqA1[idx] = u1;
                g_wqA2[idx] = u2;
            } else {
                uint2 ua1, ua2, ub1, ub2;
                split2pack(w0, w1, ua1.x, ua2.x);
                split2pack(w4, w5, ua1.y, ua2.y);
                split2pack(w2, w3, ub1.x, ub2.x);
                split2pack(w6, w7, ub1.y, ub2.y);
                const size_t ia = ((bh * 128 + q16 * 2) * 4 + k16) * 32 + lane;
                const size_t ib = ((bh * 128 + q16 * 2 + 1) * 4 + k16) * 32 + lane;
                g_wkB1[ia] = ua1; g_wkB2[ia] = ua2;
                g_wkB1[ib] = ub1; g_wkB2[ib] = ub2;
            }
        }
    }
}

// ---------------------------------------------------------------------------
// Kernel 2: V -> B-fragment layout (unchanged).
// ---------------------------------------------------------------------------
__global__ __launch_bounds__(256) void vsplit_kernel(const float* __restrict__ value) {
    __shared__ float t[32][33];
    const int tid = threadIdx.x;
    const int f0 = blockIdx.x * 32, s0 = blockIdx.y * 32, b = blockIdx.z;

    for (int u = tid; u < 1024; u += 256) {
        int s = u >> 5, f = u & 31;
        t[s][f] = value[(size_t)(s0 + s) * (BB * FF) + b * FF + f0 + f];
    }
    __syncthreads();

    const int blk = tid >> 5, lane = tid & 31;
    const int sbk = blk >> 2, fb = blk & 3;
    const int g = lane >> 2, tig = lane & 3;
    const int s_l = sbk * 16 + tig * 2;
    const int f_l = fb * 8 + g;
    __half2 bh0 = __floats2half2_rn(t[s_l][f_l], t[s_l + 1][f_l]);
    __half2 bh1 = __floats2half2_rn(t[s_l + 8][f_l], t[s_l + 9][f_l]);
    uint2 u;
    u.x = *(uint32_t*)&bh0; u.y = *(uint32_t*)&bh1;
    const int f8 = (f0 >> 3) + fb;
    const int s16 = (s0 >> 4) + sbk;
    ((uint2*)g_vt)[(((size_t)b * 64 + f8) * 64 + s16) * 32 + lane] = u;
}

// ---------------------------------------------------------------------------
// Kernel 3 (FUSED, v2): CTA = 32q x 512f, 256 thr (8 warps), 2 CTAs/SM.
// 2 syncthreads per s-chunk; double-buffered running-max & partial-sums;
// every thread computes its rows' Mn/rescale locally.
// ---------------------------------------------------------------------------
#define FWQ   0        // 8192: wq frag blobs [q16l 2][kc 4][p 2] x 512B
#define FPB   8192     // 8192: P frag blobs [q16l 2][s16l 8] x 512B
#define FM    16384    // 2 x 32 x 4 = 256: running max, double-buffered
#define FL    16640    // 128: running sum
#define FSMAX 16768    // 32*9*4 = 1152: chunk-max partials
#define FPS   17920    // 2 x 32*9*4 = 2304: p-sum partials, double-buffered
#define FUSED_SMEM 20224

__global__ __launch_bounds__(256, 2) void attn_kernel(float* __restrict__ out) {
    const int tid = threadIdx.x;
    const int xw = tid >> 5, lane = tid & 31;
    const int g = lane >> 2, tig = lane & 3;
    const int qt = blockIdx.x;           // 0..31 (32 q each)
    const int h = blockIdx.y, b = blockIdx.z;
    const size_t bh = (size_t)b * HH + h;

    float* sm_m   = (float*)(smx + FM);     // [2][32]
    float* sm_l   = (float*)(smx + FL);     // [32]
    float* sm_max = (float*)(smx + FSMAX);  // [32][9]
    float* sm_ps  = (float*)(smx + FPS);    // [2][32][9]

    // prologue: stage wq A-frags (2 q16 x 4 kc x 2 parts)
    for (int u = tid; u < 512; u += 256) {
        const int q16l = u >> 8, kc = (u >> 6) & 3, p = (u >> 5) & 1, ln = u & 31;
        const uint4* src = (p ? g_wqA2 : g_wqA1) +
            ((bh * 64 + qt * 2 + q16l) * 4 + kc) * 32 + ln;
        *(uint4*)(smx + FWQ + u * 16) = *src;
    }
    if (tid < 64) sm_m[tid] = -1e30f;       // both parities
    if (tid < 32) sm_l[tid] = 0.f;
    for (int u = tid; u < 2 * 32 * 9; u += 256) sm_ps[u] = 0.f;
    __syncthreads();

    float oacc[2][8][4] = {};

    for (int sc = 0; sc < 8; sc++) {
        const int pw = sc & 1, pr = pw ^ 1;

        // ---- S phase: warp computes S[32q x 16s] at s16 = sc*8 + xw ----
        float sacc[2][2][4] = {};
#pragma unroll
        for (int kc = 0; kc < 4; kc++) {
            uint4 a[2][2];
#pragma unroll
            for (int mi = 0; mi < 2; mi++)
#pragma unroll
                for (int p = 0; p < 2; p++)
                    a[mi][p] = *(const uint4*)(smx + FWQ +
                        ((mi * 4 + kc) * 2 + p) * 512 + lane * 16);
#pragma unroll
            for (int nj = 0; nj < 2; nj++) {
                const int n8 = (sc * 8 + xw) * 2 + nj;
                const size_t ib = ((bh * 128 + n8) * 4 + kc) * 32 + lane;
                uint2 B1 = g_wkB1[ib];
                uint2 B2 = g_wkB2[ib];
#pragma unroll
                for (int mi = 0; mi < 2; mi++) {
                    mma_bf16(sacc[mi][nj], a[mi][0].x, a[mi][0].y, a[mi][0].z, a[mi][0].w, B1.x, B1.y);
                    mma_bf16(sacc[mi][nj], a[mi][0].x, a[mi][0].y, a[mi][0].z, a[mi][0].w, B2.x, B2.y);
                    mma_bf16(sacc[mi][nj], a[mi][1].x, a[mi][1].y, a[mi][1].z, a[mi][1].w, B1.x, B1.y);
                }
            }
        }

        // ---- chunk-max partials ----
#pragma unroll
        for (int mi = 0; mi < 2; mi++) {
            float rm0 = fmaxf(fmaxf(sacc[mi][0][0], sacc[mi][0][1]),
                              fmaxf(sacc[mi][1][0], sacc[mi][1][1]));
            float rm1 = fmaxf(fmaxf(sacc[mi][0][2], sacc[mi][0][3]),
                              fmaxf(sacc[mi][1][2], sacc[mi][1][3]));
            rm0 = fmaxf(rm0, __shfl_xor_sync(0xFFFFFFFFu, rm0, 1));
            rm0 = fmaxf(rm0, __shfl_xor_sync(0xFFFFFFFFu, rm0, 2));
            rm1 = fmaxf(rm1, __shfl_xor_sync(0xFFFFFFFFu, rm1, 1));
            rm1 = fmaxf(rm1, __shfl_xor_sync(0xFFFFFFFFu, rm1, 2));
            if (tig == 0) {
                sm_max[(mi * 16 + g) * 9 + xw] = rm0;
                sm_max[(mi * 16 + g + 8) * 9 + xw] = rm1;
            }
        }
        __syncthreads();   // sync A

        // ---- local Mn / rescale for this thread's 4 rows; owner updates state ----
        float mn[2][2], scl[2][2];
#pragma unroll
        for (int mi = 0; mi < 2; mi++)
#pragma unroll
            for (int half = 0; half < 2; half++) {
                const int r = mi * 16 + g + half * 8;
                const float* mx = sm_max + r * 9;
                float cm = fmaxf(fmaxf(fmaxf(mx[0], mx[1]), fmaxf(mx[2], mx[3])),
                                 fmaxf(fmaxf(mx[4], mx[5]), fmaxf(mx[6], mx[7])));
                float Mo = sm_m[pr * 32 + r];
                float Mn = fmaxf(Mo, cm);
                mn[mi][half] = Mn;
                scl[mi][half] = __expf(Mo - Mn);
            }
        if (tid < 32) {
            const float* px = sm_ps + pr * 288 + tid * 9;
            float ps = px[0] + px[1] + px[2] + px[3] + px[4] + px[5] + px[6] + px[7];
            const float* mx = sm_max + tid * 9;
            float cm = fmaxf(fmaxf(fmaxf(mx[0], mx[1]), fmaxf(mx[2], mx[3])),
                             fmaxf(fmaxf(mx[4], mx[5]), fmaxf(mx[6], mx[7])));
            float Mo = sm_m[pr * 32 + tid];
            float Mn = fmaxf(Mo, cm);
            sm_m[pw * 32 + tid] = Mn;
            sm_l[tid] = (sm_l[tid] + ps) * __expf(Mo - Mn);
        }

        // ---- P = exp(s - Mn) -> fp16 A-frags; p-sum partials; rescale oacc ----
#pragma unroll
        for (int mi = 0; mi < 2; mi++) {
            float e[2][4];
#pragma unroll
            for (int nj = 0; nj < 2; nj++) {
                e[nj][0] = __expf(sacc[mi][nj][0] - mn[mi][0]);
                e[nj][1] = __expf(sacc[mi][nj][1] - mn[mi][0]);
                e[nj][2] = __expf(sacc[mi][nj][2] - mn[mi][1]);
                e[nj][3] = __expf(sacc[mi][nj][3] - mn[mi][1]);
            }
            float p0 = e[0][0] + e[0][1] + e[1][0] + e[1][1];
            float p1 = e[0][2] + e[0][3] + e[1][2] + e[1][3];
            p0 += __shfl_xor_sync(0xFFFFFFFFu, p0, 1);
            p0 += __shfl_xor_sync(0xFFFFFFFFu, p0, 2);
            p1 += __shfl_xor_sync(0xFFFFFFFFu, p1, 1);
            p1 += __shfl_xor_sync(0xFFFFFFFFu, p1, 2);
            if (tig == 0) {
                sm_ps[pw * 288 + (mi * 16 + g) * 9 + xw] = p0;
                sm_ps[pw * 288 + (mi * 16 + g + 8) * 9 + xw] = p1;
            }
            __half2 h0 = __floats2half2_rn(e[0][0], e[0][1]);
            __half2 h1 = __floats2half2_rn(e[0][2], e[0][3]);
            __half2 h2 = __floats2half2_rn(e[1][0], e[1][1]);
            __half2 h3 = __floats2half2_rn(e[1][2], e[1][3]);
            uint4 u;
            u.x = *(uint32_t*)&h0; u.y = *(uint32_t*)&h1;
            u.z = *(uint32_t*)&h2; u.w = *(uint32_t*)&h3;
            *(uint4*)(smx + FPB + (mi * 8 + xw) * 512 + lane * 16) = u;

#pragma unroll
            for (int ni = 0; ni < 8; ni++) {
                oacc[mi][ni][0] *= scl[mi][0]; oacc[mi][ni][1] *= scl[mi][0];
                oacc[mi][ni][2] *= scl[mi][1]; oacc[mi][ni][3] *= scl[mi][1];
            }
        }
        __syncthreads();   // sync B

        // ---- PV phase: warp = 32q x 64f (f8 = xw*8 + ni) ----
#pragma unroll
        for (int kk = 0; kk < 8; kk++) {
            uint4 au0 = *(const uint4*)(smx + FPB + kk * 512 + lane * 16);
            uint4 au1 = *(const uint4*)(smx + FPB + (8 + kk) * 512 + lane * 16);
#pragma unroll
            for (int ni = 0; ni < 8; ni++) {
                uint2 v = ((const uint2*)g_vt)[
                    (((size_t)b * 64 + xw * 8 + ni) * 64 + sc * 8 + kk) * 32 + lane];
                mma_f16(oacc[0][ni], au0.x, au0.y, au0.z, au0.w, v.x, v.y);
                mma_f16(oacc[1][ni], au1.x, au1.y, au1.z, au1.w, v.x, v.y);
            }
        }
        __syncthreads();   // protects P-frags & sm_max for next chunk
    }

    // ---- epilogue: final inverse row sums (local), scale, store ----
    float iv[2][2];
#pragma unroll
    for (int mi = 0; mi < 2; mi++)
#pragma unroll
        for (int half = 0; half < 2; half++) {
            const int r = mi * 16 + g + half * 8;
            const float* px = sm_ps + 288 + r * 9;   // parity of sc=7 is 1
            float ps = px[0] + px[1] + px[2] + px[3] + px[4] + px[5] + px[6] + px[7];
            iv[mi][half] = 1.0f / (sm_l[r] + ps);
        }

#pragma unroll
    for (int mi = 0; mi < 2; mi++) {
        const int q0 = qt * 32 + mi * 16 + g;
#pragma unroll
        for (int ni = 0; ni < 8; ni++) {
            const int f = (xw * 8 + ni) * 8 + tig * 2;
            float* op0 = out + ((size_t)q0 * BB + b) * (HH * FF) + h * FF + f;
            float* op1 = out + ((size_t)(q0 + 8) * BB + b) * (HH * FF) + h * FF + f;
            *(float2*)op0 = make_float2(oacc[mi][ni][0] * iv[mi][0], oacc[mi][ni][1] * iv[mi][0]);
            *(float2*)op1 = make_float2(oacc[mi][ni][2] * iv[mi][1], oacc[mi][ni][3] * iv[mi][1]);
        }
    }
}

// ---------------------------------------------------------------------------
extern "C" void kernel_launch(void* const* d_in, const int* in_sizes, int n_in,
                              void* d_out, int out_size) {
    const float* query = (const float*)d_in[0];
    const float* key   = (const float*)d_in[1];
    const float* value = (const float*)d_in[2];
    const float* Wk    = (const float*)d_in[3];
    const float* bk    = (const float*)d_in[4];
    float* out = (float*)d_out;

    cudaFuncSetAttribute(projmma_kernel, cudaFuncAttributeMaxDynamicSharedMemorySize, PROJ_SMEM);
    dim3 pg(8 * 16, HH, 2);
    projmma_kernel<<<pg, 256, PROJ_SMEM>>>(query, key, Wk, bk);

    dim3 vg(FF / 32, LQ / 32, BB);
    vsplit_kernel<<<vg, 256>>>(value);

    cudaFuncSetAttribute(attn_kernel, cudaFuncAttributeMaxDynamicSharedMemorySize, FUSED_SMEM);
    dim3 ag(32, HH, BB);   // (qt, h, b) = 4096 CTAs
    attn_kernel<<<ag, 256, FUSED_SMEM>>>(out);
}

// round 16
// speedup vs baseline: 6.5197x; 1.1172x over previous
#include <cuda_runtime.h>
#include <cuda_bf16.h>
#include <cuda_fp16.h>
#include <math.h>
#include <stdint.h>

#define LQ 1024
#define BB 16
#define FF 512
#define HH 8
#define KK 64
#define TEMPS 30.0f
#define BH 128

// ------------------------- static scratch -------------------------
// X (query/key) as split-bf16 A-fragments: [inp][b][q16 0..63][kc 0..31][lane] uint4
__device__ __align__(16) uint4 g_xA1[(size_t)2 * 16 * 64 * 32 * 32];
__device__ __align__(16) uint4 g_xA2[(size_t)2 * 16 * 64 * 32 * 32];
// W as split-bf16 B-fragments: [n8 0..63][kc 0..31][lane] uint2
__device__ __align__(16) uint2 g_wB1[(size_t)64 * 32 * 32];
__device__ __align__(16) uint2 g_wB2[(size_t)64 * 32 * 32];
// wq as A-fragments: [bh][q16 0..63][k16 0..3][lane] uint4, 2 parts
__device__ __align__(16) uint4 g_wqA1[(size_t)BH * 64 * 4 * 32];
__device__ __align__(16) uint4 g_wqA2[(size_t)BH * 64 * 4 * 32];
// wk as B-fragments: [bh][n8 0..127][k16 0..3][lane] uint2, 2 parts
__device__ __align__(16) uint2 g_wkB1[(size_t)BH * 128 * 4 * 32];
__device__ __align__(16) uint2 g_wkB2[(size_t)BH * 128 * 4 * 32];
// V (hi fp16) B-fragments: [b][f8 0..63][s16 0..63][lane] uint2
__device__ __align__(16) uint32_t g_vt[(size_t)BB * 64 * 64 * 32 * 2];

// ------------------------- helpers -------------------------
__device__ __forceinline__ void split2pack(float x, float y, uint32_t& hi, uint32_t& lo) {
    __nv_bfloat16 hx = __float2bfloat16(x), hy = __float2bfloat16(y);
    __nv_bfloat16 lx = __float2bfloat16(x - __bfloat162float(hx));
    __nv_bfloat16 ly = __float2bfloat16(y - __bfloat162float(hy));
    __nv_bfloat162 H = __halves2bfloat162(hx, hy);
    __nv_bfloat162 L = __halves2bfloat162(lx, ly);
    hi = *(uint32_t*)&H;
    lo = *(uint32_t*)&L;
}
__device__ __forceinline__ void mma_bf16(float c[4], uint32_t a0, uint32_t a1, uint32_t a2,
                                         uint32_t a3, uint32_t b0, uint32_t b1) {
    asm("mma.sync.aligned.m16n8k16.row.col.f32.bf16.bf16.f32 "
        "{%0,%1,%2,%3}, {%4,%5,%6,%7}, {%8,%9}, {%0,%1,%2,%3};"
        : "+f"(c[0]), "+f"(c[1]), "+f"(c[2]), "+f"(c[3])
        : "r"(a0), "r"(a1), "r"(a2), "r"(a3), "r"(b0), "r"(b1));
}
__device__ __forceinline__ void mma_f16(float c[4], uint32_t a0, uint32_t a1, uint32_t a2,
                                        uint32_t a3, uint32_t b0, uint32_t b1) {
    asm("mma.sync.aligned.m16n8k16.row.col.f32.f16.f16.f32 "
        "{%0,%1,%2,%3}, {%4,%5,%6,%7}, {%8,%9}, {%0,%1,%2,%3};"
        : "+f"(c[0]), "+f"(c[1]), "+f"(c[2]), "+f"(c[3])
        : "r"(a0), "r"(a1), "r"(a2), "r"(a3), "r"(b0), "r"(b1));
}
extern __shared__ __align__(1024) char smx[];

// ---------------------------------------------------------------------------
// Kernel 0a: W -> split-bf16 B-fragments. grid(64 n8), 256 thr.
// ---------------------------------------------------------------------------
__global__ __launch_bounds__(256) void wsplit_kernel(const float* __restrict__ W) {
    const int w = threadIdx.x >> 5, lane = threadIdx.x & 31;
    const int g = lane >> 2, tig = lane & 3;
    const int n8 = blockIdx.x;
    const int n = n8 * 8 + g;
#pragma unroll
    for (int u = 0; u < 4; u++) {
        const int kc = w * 4 + u;
        float2 w0 = *(const float2*)(W + (size_t)n * FF + kc * 16 + tig * 2);
        float2 w1 = *(const float2*)(W + (size_t)n * FF + kc * 16 + 8 + tig * 2);
        uint2 u1, u2;
        split2pack(w0.x, w0.y, u1.x, u2.x);
        split2pack(w1.x, w1.y, u1.y, u2.y);
        const size_t idx = ((size_t)n8 * 32 + kc) * 32 + lane;
        g_wB1[idx] = u1;
        g_wB2[idx] = u2;
    }
}

// ---------------------------------------------------------------------------
// Kernel 0b: X (query & key) -> split-bf16 A-fragments.
// grid (64 q16, 16 b, 2 inp), 256 thr; warp w handles kc = w*4..w*4+3.
// ---------------------------------------------------------------------------
__global__ __launch_bounds__(256) void xsplit_kernel(const float* __restrict__ Q,
                                                     const float* __restrict__ Kx) {
    const int w = threadIdx.x >> 5, lane = threadIdx.x & 31;
    const int g = lane >> 2, tig = lane & 3;
    const int q16 = blockIdx.x, b = blockIdx.y, inp = blockIdx.z;
    const float* X = inp ? Kx : Q;
    const int r0 = q16 * 16 + g;        // global q index
    const float* p0 = X + ((size_t)r0 * BB + b) * FF;
    const float* p1 = X + ((size_t)(r0 + 8) * BB + b) * FF;
#pragma unroll
    for (int u = 0; u < 4; u++) {
        const int kc = w * 4 + u;
        const int k0 = kc * 16 + tig * 2;
        float2 v00 = *(const float2*)(p0 + k0);
        float2 v10 = *(const float2*)(p1 + k0);
        float2 v01 = *(const float2*)(p0 + k0 + 8);
        float2 v11 = *(const float2*)(p1 + k0 + 8);
        uint4 u1, u2;
        split2pack(v00.x, v00.y, u1.x, u2.x);
        split2pack(v10.x, v10.y, u1.y, u2.y);
        split2pack(v01.x, v01.y, u1.z, u2.z);
        split2pack(v11.x, v11.y, u1.w, u2.w);
        const size_t idx = ((((size_t)inp * 16 + b) * 64 + q16) * 32 + kc) * 32 + lane;
        g_xA1[idx] = u1;
        g_xA2[idx] = u2;
    }
}

// ---------------------------------------------------------------------------
// Kernel 1: projection, fragment-native (no smem staging, no mainloop syncs).
// CTA = 128m x 64n; grid (qt*16+b, h, inp). 3 split passes.
// ---------------------------------------------------------------------------
__global__ __launch_bounds__(256) void projmma_kernel(const float* __restrict__ bias) {
    __shared__ float ssq[128][2];
    const int tid = threadIdx.x;
    const int w = tid >> 5, lane = tid & 31;
    const int g = lane >> 2, tig = lane & 3;
    const int qw = w >> 1, nw = w & 1;
    const int bx = blockIdx.x;
    const int qt = bx >> 4, b = bx & 15;
    const int h = blockIdx.y;
    const int isQ = (blockIdx.z == 0);
    const float scale = isQ ? TEMPS : 1.0f;
    const int n0 = h * 64;
    const size_t bh = (size_t)b * HH + h;
    const size_t ib_ = (size_t)blockIdx.z * 16 + b;

    float acc[2][4][4] = {};

    for (int kc = 0; kc < 32; kc++) {
        uint4 A1[2], A2[2];
#pragma unroll
        for (int mi = 0; mi < 2; mi++) {
            const size_t ia = ((ib_ * 64 + qt * 8 + qw * 2 + mi) * 32 + kc) * 32 + lane;
            A1[mi] = g_xA1[ia];
            A2[mi] = g_xA2[ia];
        }
#pragma unroll
        for (int j = 0; j < 2; j++) {
#pragma unroll
            for (int nn = 0; nn < 2; nn++) {
                const int n8 = h * 8 + nw * 4 + j * 2 + nn;
                const size_t ibx = ((size_t)n8 * 32 + kc) * 32 + lane;
                uint2 B1 = g_wB1[ibx];
                uint2 B2 = g_wB2[ibx];
#pragma unroll
                for (int mi = 0; mi < 2; mi++) {
                    float* c = acc[mi][2 * j + nn];
                    mma_bf16(c, A1[mi].x, A1[mi].y, A1[mi].z, A1[mi].w, B1.x, B1.y);
                    mma_bf16(c, A1[mi].x, A1[mi].y, A1[mi].z, A1[mi].w, B2.x, B2.y);
                    mma_bf16(c, A2[mi].x, A2[mi].y, A2[mi].z, A2[mi].w, B1.x, B1.y);
                }
            }
        }
    }

    // bias
#pragma unroll
    for (int ni = 0; ni < 4; ni++) {
        float2 bb = *(const float2*)(bias + n0 + nw * 32 + ni * 8 + tig * 2);
#pragma unroll
        for (int mi = 0; mi < 2; mi++) {
            acc[mi][ni][0] += bb.x; acc[mi][ni][1] += bb.y;
            acc[mi][ni][2] += bb.x; acc[mi][ni][3] += bb.y;
        }
    }

    // ssq partials, reduce over tig, cross-nw via smem
#pragma unroll
    for (int mi = 0; mi < 2; mi++) {
        float s0 = 0.f, s1 = 0.f;
#pragma unroll
        for (int ni = 0; ni < 4; ni++) {
            s0 = fmaf(acc[mi][ni][0], acc[mi][ni][0], s0);
            s0 = fmaf(acc[mi][ni][1], acc[mi][ni][1], s0);
            s1 = fmaf(acc[mi][ni][2], acc[mi][ni][2], s1);
            s1 = fmaf(acc[mi][ni][3], acc[mi][ni][3], s1);
        }
        s0 += __shfl_xor_sync(0xFFFFFFFFu, s0, 1);
        s0 += __shfl_xor_sync(0xFFFFFFFFu, s0, 2);
        s1 += __shfl_xor_sync(0xFFFFFFFFu, s1, 1);
        s1 += __shfl_xor_sync(0xFFFFFFFFu, s1, 2);
        if (tig == 0) {
            ssq[qw * 32 + mi * 16 + g][nw] = s0;
            ssq[qw * 32 + mi * 16 + g + 8][nw] = s1;
        }
    }
    __syncthreads();

#pragma unroll
    for (int mi = 0; mi < 2; mi++) {
        const int rg = qw * 32 + mi * 16 + g;
        const float sc0 = scale / fmaxf(sqrtf(ssq[rg][0] + ssq[rg][1]), 1e-12f);
        const float sc1 = scale / fmaxf(sqrtf(ssq[rg + 8][0] + ssq[rg + 8][1]), 1e-12f);
        const int q16 = qt * 8 + qw * 2 + mi;
#pragma unroll
        for (int jj = 0; jj < 2; jj++) {
            const int k16 = nw * 2 + jj;
            float w0 = acc[mi][2 * jj][0] * sc0, w1 = acc[mi][2 * jj][1] * sc0;
            float w2 = acc[mi][2 * jj][2] * sc1, w3 = acc[mi][2 * jj][3] * sc1;
            float w4 = acc[mi][2 * jj + 1][0] * sc0, w5 = acc[mi][2 * jj + 1][1] * sc0;
            float w6 = acc[mi][2 * jj + 1][2] * sc1, w7 = acc[mi][2 * jj + 1][3] * sc1;
            if (isQ) {
                uint4 u1, u2;
                split2pack(w0, w1, u1.x, u2.x);
                split2pack(w2, w3, u1.y, u2.y);
                split2pack(w4, w5, u1.z, u2.z);
                split2pack(w6, w7, u1.w, u2.w);
                const size_t idx = ((bh * 64 + q16) * 4 + k16) * 32 + lane;
                g_wqA1[idx] = u1;
                g_wqA2[idx] = u2;
            } else {
                uint2 ua1, ua2, ub1, ub2;
                split2pack(w0, w1, ua1.x, ua2.x);
                split2pack(w4, w5, ua1.y, ua2.y);
                split2pack(w2, w3, ub1.x, ub2.x);
                split2pack(w6, w7, ub1.y, ub2.y);
                const size_t ia = ((bh * 128 + q16 * 2) * 4 + k16) * 32 + lane;
                const size_t ib2 = ((bh * 128 + q16 * 2 + 1) * 4 + k16) * 32 + lane;
                g_wkB1[ia] = ua1; g_wkB2[ia] = ua2;
                g_wkB1[ib2] = ub1; g_wkB2[ib2] = ub2;
            }
        }
    }
}

// ---------------------------------------------------------------------------
// Kernel 2: V -> B-fragment layout (unchanged).
// ---------------------------------------------------------------------------
__global__ __launch_bounds__(256) void vsplit_kernel(const float* __restrict__ value) {
    __shared__ float t[32][33];
    const int tid = threadIdx.x;
    const int f0 = blockIdx.x * 32, s0 = blockIdx.y * 32, b = blockIdx.z;

    for (int u = tid; u < 1024; u += 256) {
        int s = u >> 5, f = u & 31;
        t[s][f] = value[(size_t)(s0 + s) * (BB * FF) + b * FF + f0 + f];
    }
    __syncthreads();

    const int blk = tid >> 5, lane = tid & 31;
    const int sbk = blk >> 2, fb = blk & 3;
    const int g = lane >> 2, tig = lane & 3;
    const int s_l = sbk * 16 + tig * 2;
    const int f_l = fb * 8 + g;
    __half2 bh0 = __floats2half2_rn(t[s_l][f_l], t[s_l + 1][f_l]);
    __half2 bh1 = __floats2half2_rn(t[s_l + 8][f_l], t[s_l + 9][f_l]);
    uint2 u;
    u.x = *(uint32_t*)&bh0; u.y = *(uint32_t*)&bh1;
    const int f8 = (f0 >> 3) + fb;
    const int s16 = (s0 >> 4) + sbk;
    ((uint2*)g_vt)[(((size_t)b * 64 + f8) * 64 + s16) * 32 + lane] = u;
}

// ---------------------------------------------------------------------------
// Kernel 3 (FUSED, v3): CTA = 32q x 512f, 256 thr, 2 CTAs/SM.
// 2 syncthreads per s-chunk (double-buffered P-frags + chunk-max).
// ---------------------------------------------------------------------------
#define FWQ   0        // 8192: wq frag blobs
#define FPB   8192     // 2 x 8192: P frag blobs, double-buffered
#define FM    24576    // 2 x 32 x 4: running max, double-buffered
#define FL    24832    // 128: running sum
#define FSMAX 24960    // 2 x 32*9*4: chunk-max partials, double-buffered
#define FPS   27264    // 2 x 32*9*4: p-sum partials, double-buffered
#define FUSED_SMEM 29568

__global__ __launch_bounds__(256, 2) void attn_kernel(float* __restrict__ out) {
    const int tid = threadIdx.x;
    const int xw = tid >> 5, lane = tid & 31;
    const int g = lane >> 2, tig = lane & 3;
    const int qt = blockIdx.x;
    const int h = blockIdx.y, b = blockIdx.z;
    const size_t bh = (size_t)b * HH + h;

    float* sm_m   = (float*)(smx + FM);     // [2][32]
    float* sm_l   = (float*)(smx + FL);     // [32]
    float* sm_max = (float*)(smx + FSMAX);  // [2][32][9]
    float* sm_ps  = (float*)(smx + FPS);    // [2][32][9]

    for (int u = tid; u < 512; u += 256) {
        const int q16l = u >> 8, kc = (u >> 6) & 3, p = (u >> 5) & 1, ln = u & 31;
        const uint4* src = (p ? g_wqA2 : g_wqA1) +
            ((bh * 64 + qt * 2 + q16l) * 4 + kc) * 32 + ln;
        *(uint4*)(smx + FWQ + u * 16) = *src;
    }
    if (tid < 64) sm_m[tid] = -1e30f;
    if (tid < 32) sm_l[tid] = 0.f;
    for (int u = tid; u < 2 * 32 * 9; u += 256) sm_ps[u] = 0.f;
    __syncthreads();

    float oacc[2][8][4] = {};

    for (int sc = 0; sc < 8; sc++) {
        const int pw = sc & 1, pr = pw ^ 1;

        // ---- S phase ----
        float sacc[2][2][4] = {};
#pragma unroll
        for (int kc = 0; kc < 4; kc++) {
            uint4 a[2][2];
#pragma unroll
            for (int mi = 0; mi < 2; mi++)
#pragma unroll
                for (int p = 0; p < 2; p++)
                    a[mi][p] = *(const uint4*)(smx + FWQ +
                        ((mi * 4 + kc) * 2 + p) * 512 + lane * 16);
#pragma unroll
            for (int nj = 0; nj < 2; nj++) {
                const int n8 = (sc * 8 + xw) * 2 + nj;
                const size_t ib = ((bh * 128 + n8) * 4 + kc) * 32 + lane;
                uint2 B1 = g_wkB1[ib];
                uint2 B2 = g_wkB2[ib];
#pragma unroll
                for (int mi = 0; mi < 2; mi++) {
                    mma_bf16(sacc[mi][nj], a[mi][0].x, a[mi][0].y, a[mi][0].z, a[mi][0].w, B1.x, B1.y);
                    mma_bf16(sacc[mi][nj], a[mi][0].x, a[mi][0].y, a[mi][0].z, a[mi][0].w, B2.x, B2.y);
                    mma_bf16(sacc[mi][nj], a[mi][1].x, a[mi][1].y, a[mi][1].z, a[mi][1].w, B1.x, B1.y);
                }
            }
        }

        // ---- chunk-max partials (buffer pw) ----
#pragma unroll
        for (int mi = 0; mi < 2; mi++) {
            float rm0 = fmaxf(fmaxf(sacc[mi][0][0], sacc[mi][0][1]),
                              fmaxf(sacc[mi][1][0], sacc[mi][1][1]));
            float rm1 = fmaxf(fmaxf(sacc[mi][0][2], sacc[mi][0][3]),
                              fmaxf(sacc[mi][1][2], sacc[mi][1][3]));
            rm0 = fmaxf(rm0, __shfl_xor_sync(0xFFFFFFFFu, rm0, 1));
            rm0 = fmaxf(rm0, __shfl_xor_sync(0xFFFFFFFFu, rm0, 2));
            rm1 = fmaxf(rm1, __shfl_xor_sync(0xFFFFFFFFu, rm1, 1));
            rm1 = fmaxf(rm1, __shfl_xor_sync(0xFFFFFFFFu, rm1, 2));
            if (tig == 0) {
                sm_max[pw * 288 + (mi * 16 + g) * 9 + xw] = rm0;
                sm_max[pw * 288 + (mi * 16 + g + 8) * 9 + xw] = rm1;
            }
        }
        __syncthreads();   // sync A

        // ---- local Mn / rescale; owner updates running state ----
        float mn[2][2], scl[2][2];
#pragma unroll
        for (int mi = 0; mi < 2; mi++)
#pragma unroll
            for (int half = 0; half < 2; half++) {
                const int r = mi * 16 + g + half * 8;
                const float* mx = sm_max + pw * 288 + r * 9;
                float cm = fmaxf(fmaxf(fmaxf(mx[0], mx[1]), fmaxf(mx[2], mx[3])),
                                 fmaxf(fmaxf(mx[4], mx[5]), fmaxf(mx[6], mx[7])));
                float Mo = sm_m[pr * 32 + r];
                float Mn = fmaxf(Mo, cm);
                mn[mi][half] = Mn;
                scl[mi][half] = __expf(Mo - Mn);
            }
        if (tid < 32) {
            const float* px = sm_ps + pr * 288 + tid * 9;
            float ps = px[0] + px[1] + px[2] + px[3] + px[4] + px[5] + px[6] + px[7];
            const float* mx = sm_max + pw * 288 + tid * 9;
            float cm = fmaxf(fmaxf(fmaxf(mx[0], mx[1]), fmaxf(mx[2], mx[3])),
                             fmaxf(fmaxf(mx[4], mx[5]), fmaxf(mx[6], mx[7])));
            float Mo = sm_m[pr * 32 + tid];
            float Mn = fmaxf(Mo, cm);
            sm_m[pw * 32 + tid] = Mn;
            sm_l[tid] = (sm_l[tid] + ps) * __expf(Mo - Mn);
        }

        // ---- P = exp(s - Mn) -> fp16 A-frags (buffer pw); rescale oacc ----
#pragma unroll
        for (int mi = 0; mi < 2; mi++) {
            float e[2][4];
#pragma unroll
            for (int nj = 0; nj < 2; nj++) {
                e[nj][0] = __expf(sacc[mi][nj][0] - mn[mi][0]);
                e[nj][1] = __expf(sacc[mi][nj][1] - mn[mi][0]);
                e[nj][2] = __expf(sacc[mi][nj][2] - mn[mi][1]);
                e[nj][3] = __expf(sacc[mi][nj][3] - mn[mi][1]);
            }
            float p0 = e[0][0] + e[0][1] + e[1][0] + e[1][1];
            float p1 = e[0][2] + e[0][3] + e[1][2] + e[1][3];
            p0 += __shfl_xor_sync(0xFFFFFFFFu, p0, 1);
            p0 += __shfl_xor_sync(0xFFFFFFFFu, p0, 2);
            p1 += __shfl_xor_sync(0xFFFFFFFFu, p1, 1);
            p1 += __shfl_xor_sync(0xFFFFFFFFu, p1, 2);
            if (tig == 0) {
                sm_ps[pw * 288 + (mi * 16 + g) * 9 + xw] = p0;
                sm_ps[pw * 288 + (mi * 16 + g + 8) * 9 + xw] = p1;
            }
            __half2 h0 = __floats2half2_rn(e[0][0], e[0][1]);
            __half2 h1 = __floats2half2_rn(e[0][2], e[0][3]);
            __half2 h2 = __floats2half2_rn(e[1][0], e[1][1]);
            __half2 h3 = __floats2half2_rn(e[1][2], e[1][3]);
            uint4 u;
            u.x = *(uint32_t*)&h0; u.y = *(uint32_t*)&h1;
            u.z = *(uint32_t*)&h2; u.w = *(uint32_t*)&h3;
            *(uint4*)(smx + FPB + pw * 8192 + (mi * 8 + xw) * 512 + lane * 16) = u;

#pragma unroll
            for (int ni = 0; ni < 8; ni++) {
                oacc[mi][ni][0] *= scl[mi][0]; oacc[mi][ni][1] *= scl[mi][0];
                oacc[mi][ni][2] *= scl[mi][1]; oacc[mi][ni][3] *= scl[mi][1];
            }
        }
        __syncthreads();   // sync B

        // ---- PV phase (reads P buffer pw; no trailing sync) ----
#pragma unroll
        for (int kk = 0; kk < 8; kk++) {
            uint4 au0 = *(const uint4*)(smx + FPB + pw * 8192 + kk * 512 + lane * 16);
            uint4 au1 = *(const uint4*)(smx + FPB + pw * 8192 + (8 + kk) * 512 + lane * 16);
#pragma unroll
            for (int ni = 0; ni < 8; ni++) {
                uint2 v = ((const uint2*)g_vt)[
                    (((size_t)b * 64 + xw * 8 + ni) * 64 + sc * 8 + kk) * 32 + lane];
                mma_f16(oacc[0][ni], au0.x, au0.y, au0.z, au0.w, v.x, v.y);
                mma_f16(oacc[1][ni], au1.x, au1.y, au1.z, au1.w, v.x, v.y);
            }
        }
    }

    // ---- epilogue (all smem reads ordered by each thread's last sync B) ----
    float iv[2][2];
#pragma unroll
    for (int mi = 0; mi < 2; mi++)
#pragma unroll
        for (int half = 0; half < 2; half++) {
            const int r = mi * 16 + g + half * 8;
            const float* px = sm_ps + 288 + r * 9;   // parity of sc=7 is 1
            float ps = px[0] + px[1] + px[2] + px[3] + px[4] + px[5] + px[6] + px[7];
            iv[mi][half] = 1.0f / (sm_l[r] + ps);
        }

#pragma unroll
    for (int mi = 0; mi < 2; mi++) {
        const int q0 = qt * 32 + mi * 16 + g;
#pragma unroll
        for (int ni = 0; ni < 8; ni++) {
            const int f = (xw * 8 + ni) * 8 + tig * 2;
            float* op0 = out + ((size_t)q0 * BB + b) * (HH * FF) + h * FF + f;
            float* op1 = out + ((size_t)(q0 + 8) * BB + b) * (HH * FF) + h * FF + f;
            *(float2*)op0 = make_float2(oacc[mi][ni][0] * iv[mi][0], oacc[mi][ni][1] * iv[mi][0]);
            *(float2*)op1 = make_float2(oacc[mi][ni][2] * iv[mi][1], oacc[mi][ni][3] * iv[mi][1]);
        }
    }
}

// ---------------------------------------------------------------------------
extern "C" void kernel_launch(void* const* d_in, const int* in_sizes, int n_in,
                              void* d_out, int out_size) {
    const float* query = (const float*)d_in[0];
    const float* key   = (const float*)d_in[1];
    const float* value = (const float*)d_in[2];
    const float* Wk    = (const float*)d_in[3];
    const float* bk    = (const float*)d_in[4];
    float* out = (float*)d_out;

    wsplit_kernel<<<64, 256>>>(Wk);
    dim3 xg(64, 16, 2);
    xsplit_kernel<<<xg, 256>>>(query, key);

    dim3 pg(8 * 16, HH, 2);
    projmma_kernel<<<pg, 256>>>(bk);

    dim3 vg(FF / 32, LQ / 32, BB);
    vsplit_kernel<<<vg, 256>>>(value);

    cudaFuncSetAttribute(attn_kernel, cudaFuncAttributeMaxDynamicSharedMemorySize, FUSED_SMEM);
    dim3 ag(32, HH, BB);
    attn_kernel<<<ag, 256, FUSED_SMEM>>>(out);
}